// round 13
// baseline (speedup 1.0000x reference)
#include <cuda_runtime.h>
#include <cuda_bf16.h>
#include <cstdint>

#define F_IN  1024
#define F_H   128
#define EPS   1e-5f
#define NODES_MAX 50048
#define EDGES_MAX 800000
#define SCAN_BLOCKS 256   // >= ceil(N/256)

// ------------------------- scratch (__device__ globals) ---------------------
__device__ __align__(256) __nv_bfloat16 g_msg[NODES_MAX * F_H];
__device__ __align__(256) __nv_bfloat16 g_res[NODES_MAX * F_H];
__device__ __align__(256) __nv_bfloat16 g_Hbf[NODES_MAX * F_H];
__device__ __align__(256) __nv_bfloat16 g_W0t [F_H * F_IN];
__device__ __align__(256) __nv_bfloat16 g_Wr0t[F_H * F_IN];
__device__ __align__(256) __nv_bfloat16 g_W1t [F_H * F_H];
__device__ __align__(256) __nv_bfloat16 g_Wr1t[F_H * F_H];
__device__ int g_deg [NODES_MAX];
__device__ int g_row [NODES_MAX];
__device__ int g_cur [NODES_MAX];
__device__ int g_esrc[EDGES_MAX];
__device__ unsigned int g_stat[SCAN_BLOCKS];   // lookback: (status<<30)|value

// ------------------------- weight conversion --------------------------------
// converts two [K,128] fp32 matrices to [128,K] bf16 (k contiguous)
template <int K>
__global__ void convW_kernel(const float* __restrict__ wa, __nv_bfloat16* __restrict__ wta,
                             const float* __restrict__ wb, __nv_bfloat16* __restrict__ wtb)
{
    constexpr int HALF = K * F_H / 256;
    int b = blockIdx.x;
    const float* w = (b < HALF) ? wa : wb;
    __nv_bfloat16* wt = (b < HALF) ? wta : wtb;
    if (b >= HALF) b -= HALF;
    int idx = b * 256 + threadIdx.x;
    int k = idx >> 7, n = idx & 127;
    wt[(size_t)n * K + k] = __float2bfloat16(w[idx]);
}

// ------------------------- CSR build (side stream) --------------------------
__global__ void zero_kernel(int N)
{
    int i = blockIdx.x * blockDim.x + threadIdx.x;
    if (i < N) g_deg[i] = 0;
    if (i < SCAN_BLOCKS) g_stat[i] = 0;
}
__global__ void hist_kernel(const int* __restrict__ dst, int E)
{
    int e = blockIdx.x * blockDim.x + threadIdx.x;
    if (e < E) atomicAdd(&g_deg[dst[e]], 1);
}
__global__ void scan_kernel(int N)
{
    __shared__ int s[256];
    __shared__ int s_prefix;
    const int t = threadIdx.x;
    const int bid = blockIdx.x;
    const int i = bid * 256 + t;
    int v = (i < N) ? g_deg[i] : 0;
    s[t] = v;
    __syncthreads();
#pragma unroll
    for (int off = 1; off < 256; off <<= 1) {
        int x = (t >= off) ? s[t - off] : 0;
        __syncthreads();
        s[t] += x;
        __syncthreads();
    }
    const int total = s[255];

    if (t == 0) {
        if (bid == 0) {
            __threadfence();
            atomicExch(&g_stat[0], (2u << 30) | (unsigned)total);
            s_prefix = 0;
        } else {
            __threadfence();
            atomicExch(&g_stat[bid], (1u << 30) | (unsigned)total);
            int ex = 0;
            int j = bid - 1;
            while (true) {
                unsigned w = atomicAdd(&g_stat[j], 0u);
                unsigned st = w >> 30;
                if (st == 0) continue;
                ex += (int)(w & 0x3FFFFFFFu);
                if (st == 2u) break;
                j--;
            }
            __threadfence();
            atomicExch(&g_stat[bid], (2u << 30) | (unsigned)(ex + total));
            s_prefix = ex;
        }
    }
    __syncthreads();
    if (i < N) {
        int r = s[t] - v + s_prefix;
        g_row[i] = r;
        g_cur[i] = r;
    }
}
__global__ void fill_kernel(const int* __restrict__ src, const int* __restrict__ dst, int E)
{
    int e = blockIdx.x * blockDim.x + threadIdx.x;
    if (e >= E) return;
    int d = dst[e];
    int pos = atomicAdd(&g_cur[d], 1);
    g_esrc[pos] = src[e];
}

// ------------------------- mma helper ---------------------------------------
__device__ __forceinline__ void mma_bf16(float* c, const uint32_t* a, const uint32_t* b)
{
    asm volatile(
        "mma.sync.aligned.m16n8k16.row.col.f32.bf16.bf16.f32 "
        "{%0,%1,%2,%3}, {%4,%5,%6,%7}, {%8,%9}, {%0,%1,%2,%3};"
        : "+f"(c[0]), "+f"(c[1]), "+f"(c[2]), "+f"(c[3])
        : "r"(a[0]), "r"(a[1]), "r"(a[2]), "r"(a[3]), "r"(b[0]), "r"(b[1]));
}

// ------------------------- GEMM0: fp32 X, fused convert, BK=64 --------------
// BM=128, 256 thr, 8 warps 2(M)x4(N), dual output, single fp32 A read.
// BK=64: 16 iters -> half the syncs/commits of BK=32. A reg-staged 2 ahead
// (32 fp32/thread) -> bf16 -> double-buffered smem A. W/R 2-stage cp.async.
__global__ void __launch_bounds__(256) gemm0_kernel(
    const float* __restrict__ Xf, const __nv_bfloat16* __restrict__ Wt,
    const __nv_bfloat16* __restrict__ Wrt, const float* __restrict__ br,
    __nv_bfloat16* __restrict__ out_msg, __nv_bfloat16* __restrict__ out_res, int M)
{
    constexpr int KD = F_IN, BM = 128, BK = 64;
    constexpr int NIT = KD / BK;      // 16
    constexpr int SA = 72;            // bf16 row stride (64 + 8 pad)
    constexpr int TILE = BM * SA;     // 9216 bf16 per stage
    extern __shared__ __align__(16) __nv_bfloat16 smem[];
    __nv_bfloat16* sA = smem;                 // 2 stages
    __nv_bfloat16* sW = smem + 2 * TILE;      // 2 stages
    __nv_bfloat16* sR = smem + 4 * TILE;      // 2 stages

    const int t = threadIdx.x;
    const int bm = blockIdx.x * BM;
    const int lane = t & 31;
    const int w    = t >> 5;
    const int wm   = (w & 1) * 64;
    const int wn   = (w >> 1) * 32;
    const int g    = lane >> 2;
    const int t4   = lane & 3;

    const uint32_t sA_u = (uint32_t)__cvta_generic_to_shared(sA);
    const uint32_t sW_u = (uint32_t)__cvta_generic_to_shared(sW);
    const uint32_t sR_u = (uint32_t)__cvta_generic_to_shared(sR);

    // A staging: row = t&127, half = t>>7 (32 fp32 each)
    const int arow = t & 127;
    const int ah   = t >> 7;
    const bool aok = (bm + arow) < M;
    const float* aptr_base = Xf + (size_t)(bm + arow) * KD + ah * 32;

    float4 areg[8];
    auto loadA = [&](int it) {
        const float4* p = (const float4*)(aptr_base + it * BK);
        if (aok) {
#pragma unroll
            for (int i = 0; i < 8; i++) areg[i] = p[i];
        } else {
#pragma unroll
            for (int i = 0; i < 8; i++) areg[i] = make_float4(0, 0, 0, 0);
        }
    };
    auto convA = [&](int stg) {
        uint32_t u[16];
#pragma unroll
        for (int i = 0; i < 8; i++) {
            __nv_bfloat162 p;
            p = __float22bfloat162_rn(make_float2(areg[i].x, areg[i].y));
            u[i * 2]     = *(uint32_t*)&p;
            p = __float22bfloat162_rn(make_float2(areg[i].z, areg[i].w));
            u[i * 2 + 1] = *(uint32_t*)&p;
        }
        uint32_t a = sA_u + (uint32_t)((stg * TILE + arow * SA + ah * 32) * 2);
#pragma unroll
        for (int i = 0; i < 4; i++) {
            asm volatile("st.shared.v4.b32 [%0], {%1,%2,%3,%4};"
                         :: "r"(a + i * 16), "r"(u[i * 4]), "r"(u[i * 4 + 1]),
                            "r"(u[i * 4 + 2]), "r"(u[i * 4 + 3]));
        }
    };
    auto loadWR = [&](int it, int stg) {
        const int k0 = it * BK;
        // 128 rows x 8 chunks (16B) = 1024 chunks per tile; 4/thread/tile
#pragma unroll
        for (int i = 0; i < 4; i++) {
            int lin = t + i * 256;
            int m = lin >> 3, q = lin & 7;
            uint32_t doff = (uint32_t)((stg * TILE + m * SA + q * 8) * 2);
            const __nv_bfloat16* wsrc = Wt + (size_t)m * KD + k0 + q * 8;
            asm volatile("cp.async.cg.shared.global [%0], [%1], 16, 16;\n"
                         :: "r"(sW_u + doff), "l"(wsrc));
            const __nv_bfloat16* rsrc = Wrt + (size_t)m * KD + k0 + q * 8;
            asm volatile("cp.async.cg.shared.global [%0], [%1], 16, 16;\n"
                         :: "r"(sR_u + doff), "l"(rsrc));
        }
        asm volatile("cp.async.commit_group;\n");
    };

    float acc[2][4][4][4];
#pragma unroll
    for (int o = 0; o < 2; o++)
#pragma unroll
        for (int i = 0; i < 4; i++)
#pragma unroll
            for (int j = 0; j < 4; j++)
#pragma unroll
                for (int k = 0; k < 4; k++) acc[o][i][j][k] = 0.f;

    loadWR(0, 0);
    loadA(0);
    convA(0);      // A stage 0 ready (published by first sync)
    loadA(1);      // stage 1 in regs

    const int mrow = lane & 15;
    const int ksel = (lane >> 4) * 8;
    const int b_nrow = ((lane >> 4) & 1) * 8 + (lane & 7);
    const int b_koff = ((lane >> 3) & 1) * 8;

    for (int it = 0; it < NIT; ++it) {
        const int stg = it & 1;
        if (it + 1 < NIT) {
            loadWR(it + 1, stg ^ 1);
            asm volatile("cp.async.wait_group 1;\n");
        } else {
            asm volatile("cp.async.wait_group 0;\n");
        }
        __syncthreads();   // publishes sA[stg] (stored last iter / preloop) + sW/sR[stg]

        const uint32_t A_u = sA_u + (uint32_t)(stg * TILE * 2);
        const uint32_t W_u = sW_u + (uint32_t)(stg * TILE * 2);
        const uint32_t R_u = sR_u + (uint32_t)(stg * TILE * 2);

#pragma unroll
        for (int ks = 0; ks < 4; ks++) {
            const int kb = ks * 16;
            uint32_t a[4][4];
#pragma unroll
            for (int ma = 0; ma < 4; ma++) {
                uint32_t addr = A_u + (uint32_t)(((wm + ma * 16 + mrow) * SA + kb + ksel) * 2);
                asm volatile("ldmatrix.sync.aligned.m8n8.x4.shared.b16 {%0,%1,%2,%3}, [%4];"
                             : "=r"(a[ma][0]), "=r"(a[ma][1]), "=r"(a[ma][2]), "=r"(a[ma][3])
                             : "r"(addr));
            }
#pragma unroll
            for (int o = 0; o < 2; o++) {
                const uint32_t B_u = o ? R_u : W_u;
#pragma unroll
                for (int pr = 0; pr < 2; pr++) {
                    uint32_t b0, b1, b2, b3;
                    uint32_t addr = B_u + (uint32_t)(((wn + pr * 16 + b_nrow) * SA + kb + b_koff) * 2);
                    asm volatile("ldmatrix.sync.aligned.m8n8.x4.shared.b16 {%0,%1,%2,%3}, [%4];"
                                 : "=r"(b0), "=r"(b1), "=r"(b2), "=r"(b3)
                                 : "r"(addr));
                    uint32_t bl[2] = {b0, b1};
                    uint32_t bh[2] = {b2, b3};
#pragma unroll
                    for (int ma = 0; ma < 4; ma++) {
                        mma_bf16(acc[o][ma][pr * 2],     a[ma], bl);
                        mma_bf16(acc[o][ma][pr * 2 + 1], a[ma], bh);
                    }
                }
            }
        }
        // Write A for iter it+1 into the other A stage (1 sync/iter scheme).
        if (it + 1 < NIT) {
            convA(stg ^ 1);
            if (it + 2 < NIT) loadA(it + 2);
        }
    }

    // Epilogue: bf16 outputs; res gets +br then relu
#pragma unroll
    for (int o = 0; o < 2; o++) {
        __nv_bfloat16* __restrict__ out = o ? out_res : out_msg;
#pragma unroll
        for (int nb = 0; nb < 4; nb++) {
            const int col = wn + nb * 8 + 2 * t4;
            float2 brv = make_float2(0.f, 0.f);
            if (o) { brv.x = br[col]; brv.y = br[col + 1]; }
#pragma unroll
            for (int ma = 0; ma < 4; ma++) {
                int row0 = bm + wm + ma * 16 + g;
                float* c = acc[o][ma][nb];
                float2 v0 = make_float2(c[0], c[1]);
                float2 v1 = make_float2(c[2], c[3]);
                if (o) {
                    v0.x = fmaxf(v0.x + brv.x, 0.f); v0.y = fmaxf(v0.y + brv.y, 0.f);
                    v1.x = fmaxf(v1.x + brv.x, 0.f); v1.y = fmaxf(v1.y + brv.y, 0.f);
                }
                __nv_bfloat162 p0, p1;
                p0.x = __float2bfloat16(v0.x); p0.y = __float2bfloat16(v0.y);
                p1.x = __float2bfloat16(v1.x); p1.y = __float2bfloat16(v1.y);
                if (row0 < M)
                    *(__nv_bfloat162*)(out + (size_t)row0 * F_H + col) = p0;
                if (row0 + 8 < M)
                    *(__nv_bfloat162*)(out + (size_t)(row0 + 8) * F_H + col) = p1;
            }
        }
    }
}

// ------------------------- GEMM1: bf16 input, dual output (R6) --------------
// Works on a row-chunk: caller offsets Xb/out pointers; M = chunk row count.
__global__ void __launch_bounds__(256) gemm1_kernel(
    const __nv_bfloat16* __restrict__ Xb, const __nv_bfloat16* __restrict__ Wt,
    const __nv_bfloat16* __restrict__ Wrt, const float* __restrict__ br,
    __nv_bfloat16* __restrict__ out_msg, __nv_bfloat16* __restrict__ out_res, int M)
{
    constexpr int KD = F_H, BM = 128, BK = 32;
    constexpr int NIT = KD / BK;   // 4
    constexpr int SA = 40;
    constexpr int TILE = BM * SA;
    extern __shared__ __align__(16) __nv_bfloat16 smem[];
    __nv_bfloat16* sA = smem;
    __nv_bfloat16* sW = smem + 2 * TILE;
    __nv_bfloat16* sR = smem + 4 * TILE;

    const int t = threadIdx.x;
    const int bm = blockIdx.x * BM;
    const int lane = t & 31;
    const int w    = t >> 5;
    const int wm   = (w & 1) * 64;
    const int wn   = (w >> 1) * 32;
    const int g    = lane >> 2;
    const int t4   = lane & 3;

    const uint32_t sA_u = (uint32_t)__cvta_generic_to_shared(sA);
    const uint32_t sW_u = (uint32_t)__cvta_generic_to_shared(sW);
    const uint32_t sR_u = (uint32_t)__cvta_generic_to_shared(sR);

    float acc[2][4][4][4];
#pragma unroll
    for (int o = 0; o < 2; o++)
#pragma unroll
        for (int i = 0; i < 4; i++)
#pragma unroll
            for (int j = 0; j < 4; j++)
#pragma unroll
                for (int k = 0; k < 4; k++) acc[o][i][j][k] = 0.f;

    auto loadStage = [&](int it, int stg) {
        const int k0 = it * BK;
#pragma unroll
        for (int i = 0; i < 2; i++) {
            int lin = t + i * 256;
            int m = lin >> 2, q = lin & 3;
            uint32_t doff = (uint32_t)((stg * TILE + m * SA + q * 8) * 2);
            const __nv_bfloat16* asrc = Xb + (size_t)(bm + m) * KD + k0 + q * 8;
            int sz = (bm + m < M) ? 16 : 0;
            asm volatile("cp.async.cg.shared.global [%0], [%1], 16, %2;\n"
                         :: "r"(sA_u + doff), "l"(asrc), "r"(sz));
            const __nv_bfloat16* wsrc = Wt + (size_t)m * KD + k0 + q * 8;
            asm volatile("cp.async.cg.shared.global [%0], [%1], 16, 16;\n"
                         :: "r"(sW_u + doff), "l"(wsrc));
            const __nv_bfloat16* rsrc = Wrt + (size_t)m * KD + k0 + q * 8;
            asm volatile("cp.async.cg.shared.global [%0], [%1], 16, 16;\n"
                         :: "r"(sR_u + doff), "l"(rsrc));
        }
        asm volatile("cp.async.commit_group;\n");
    };

    loadStage(0, 0);

    const int mrow = lane & 15;
    const int ksel = (lane >> 4) * 8;
    const int b_nrow = ((lane >> 4) & 1) * 8 + (lane & 7);
    const int b_koff = ((lane >> 3) & 1) * 8;

    for (int it = 0; it < NIT; ++it) {
        const int stg = it & 1;
        if (it + 1 < NIT) {
            loadStage(it + 1, stg ^ 1);
            asm volatile("cp.async.wait_group 1;\n");
        } else {
            asm volatile("cp.async.wait_group 0;\n");
        }
        __syncthreads();

        const uint32_t A_u = sA_u + (uint32_t)(stg * TILE * 2);
        const uint32_t W_u = sW_u + (uint32_t)(stg * TILE * 2);
        const uint32_t R_u = sR_u + (uint32_t)(stg * TILE * 2);

#pragma unroll
        for (int ks = 0; ks < 2; ks++) {
            const int kb = ks * 16;
            uint32_t a[4][4];
#pragma unroll
            for (int ma = 0; ma < 4; ma++) {
                uint32_t addr = A_u + (uint32_t)(((wm + ma * 16 + mrow) * SA + kb + ksel) * 2);
                asm volatile("ldmatrix.sync.aligned.m8n8.x4.shared.b16 {%0,%1,%2,%3}, [%4];"
                             : "=r"(a[ma][0]), "=r"(a[ma][1]), "=r"(a[ma][2]), "=r"(a[ma][3])
                             : "r"(addr));
            }
#pragma unroll
            for (int o = 0; o < 2; o++) {
                const uint32_t B_u = o ? R_u : W_u;
#pragma unroll
                for (int pr = 0; pr < 2; pr++) {
                    uint32_t b0, b1, b2, b3;
                    uint32_t addr = B_u + (uint32_t)(((wn + pr * 16 + b_nrow) * SA + kb + b_koff) * 2);
                    asm volatile("ldmatrix.sync.aligned.m8n8.x4.shared.b16 {%0,%1,%2,%3}, [%4];"
                                 : "=r"(b0), "=r"(b1), "=r"(b2), "=r"(b3)
                                 : "r"(addr));
                    uint32_t bl[2] = {b0, b1};
                    uint32_t bh[2] = {b2, b3};
#pragma unroll
                    for (int ma = 0; ma < 4; ma++) {
                        mma_bf16(acc[o][ma][pr * 2],     a[ma], bl);
                        mma_bf16(acc[o][ma][pr * 2 + 1], a[ma], bh);
                    }
                }
            }
        }
        __syncthreads();
    }

#pragma unroll
    for (int o = 0; o < 2; o++) {
        __nv_bfloat16* __restrict__ out = o ? out_res : out_msg;
#pragma unroll
        for (int nb = 0; nb < 4; nb++) {
            const int col = wn + nb * 8 + 2 * t4;
            float2 brv = make_float2(0.f, 0.f);
            if (o) { brv.x = br[col]; brv.y = br[col + 1]; }
#pragma unroll
            for (int ma = 0; ma < 4; ma++) {
                int row0 = bm + wm + ma * 16 + g;
                float* c = acc[o][ma][nb];
                float2 v0 = make_float2(c[0], c[1]);
                float2 v1 = make_float2(c[2], c[3]);
                if (o) {
                    v0.x = fmaxf(v0.x + brv.x, 0.f); v0.y = fmaxf(v0.y + brv.y, 0.f);
                    v1.x = fmaxf(v1.x + brv.x, 0.f); v1.y = fmaxf(v1.y + brv.y, 0.f);
                }
                __nv_bfloat162 p0, p1;
                p0.x = __float2bfloat16(v0.x); p0.y = __float2bfloat16(v0.y);
                p1.x = __float2bfloat16(v1.x); p1.y = __float2bfloat16(v1.y);
                if (row0 < M)
                    *(__nv_bfloat162*)(out + (size_t)row0 * F_H + col) = p0;
                if (row0 + 8 < M)
                    *(__nv_bfloat162*)(out + (size_t)(row0 + 8) * F_H + col) = p1;
            }
        }
    }
}

// ------------------------- gather + fused epilogues -------------------------
__device__ __forceinline__ void acc_row(const __nv_bfloat16* __restrict__ base,
                                        int node, int lane, float4& a)
{
    uint2 q = __ldg((const uint2*)(base + (size_t)node * F_H) + lane);
    __nv_bfloat162 x0 = *(__nv_bfloat162*)&q.x;
    __nv_bfloat162 x1 = *(__nv_bfloat162*)&q.y;
    float2 f0 = __bfloat1622float2(x0);
    float2 f1 = __bfloat1622float2(x1);
    a.x += f0.x; a.y += f0.y; a.z += f1.x; a.w += f1.y;
}

__device__ __forceinline__ float4 gather_sum(const __nv_bfloat16* __restrict__ msg,
                                             int s, int e, int lane)
{
    float4 a0 = make_float4(0.f, 0.f, 0.f, 0.f);
    float4 a1 = make_float4(0.f, 0.f, 0.f, 0.f);
    float4 a2 = make_float4(0.f, 0.f, 0.f, 0.f);
    float4 a3 = make_float4(0.f, 0.f, 0.f, 0.f);
    int i = s;
    for (; i + 4 <= e; i += 4) {
        int u0 = __ldg(&g_esrc[i]),     u1 = __ldg(&g_esrc[i + 1]);
        int u2 = __ldg(&g_esrc[i + 2]), u3 = __ldg(&g_esrc[i + 3]);
        acc_row(msg, u0, lane, a0);
        acc_row(msg, u1, lane, a1);
        acc_row(msg, u2, lane, a2);
        acc_row(msg, u3, lane, a3);
    }
    for (; i < e; i++) acc_row(msg, __ldg(&g_esrc[i]), lane, a0);
    a0.x += a1.x + a2.x + a3.x;
    a0.y += a1.y + a2.y + a3.y;
    a0.z += a1.z + a2.z + a3.z;
    a0.w += a1.w + a2.w + a3.w;
    return a0;
}

// Nodes [n0, n1): agg -> relu(+b) + res -> BN -> bf16 h1
__global__ void gather0_kernel(const __nv_bfloat16* __restrict__ msg,
                               const __nv_bfloat16* __restrict__ res,
                               const float4* __restrict__ b4, const float4* __restrict__ g4,
                               const float4* __restrict__ be4, const float4* __restrict__ mn4,
                               const float4* __restrict__ vr4,
                               __nv_bfloat162* __restrict__ hout, int n0, int n1)
{
    int wid  = n0 + ((blockIdx.x * blockDim.x + threadIdx.x) >> 5);
    int lane = threadIdx.x & 31;
    if (wid >= n1) return;
    float4 a0 = gather_sum(msg, g_row[wid], g_cur[wid], lane);

    float4 r = make_float4(0.f, 0.f, 0.f, 0.f);
    acc_row(res, wid, lane, r);
    float4 bb = __ldg(b4 + lane);
    float4 gm = __ldg(g4 + lane);
    float4 be = __ldg(be4 + lane);
    float4 mn = __ldg(mn4 + lane);
    float4 vr = __ldg(vr4 + lane);
    float o0 = (fmaxf(a0.x + bb.x, 0.f) + r.x - mn.x) * rsqrtf(vr.x + EPS) * gm.x + be.x;
    float o1 = (fmaxf(a0.y + bb.y, 0.f) + r.y - mn.y) * rsqrtf(vr.y + EPS) * gm.y + be.y;
    float o2 = (fmaxf(a0.z + bb.z, 0.f) + r.z - mn.z) * rsqrtf(vr.z + EPS) * gm.z + be.z;
    float o3 = (fmaxf(a0.w + bb.w, 0.f) + r.w - mn.w) * rsqrtf(vr.w + EPS) * gm.w + be.w;

    __nv_bfloat162 p0, p1;
    p0.x = __float2bfloat16(o0); p0.y = __float2bfloat16(o1);
    p1.x = __float2bfloat16(o2); p1.y = __float2bfloat16(o3);
    hout[(size_t)wid * (F_H / 2) + lane * 2]     = p0;
    hout[(size_t)wid * (F_H / 2) + lane * 2 + 1] = p1;
}

__global__ void gather1_head_kernel(const __nv_bfloat16* __restrict__ msg,
                                    const __nv_bfloat16* __restrict__ res,
                                    const float4* __restrict__ b4, const float4* __restrict__ g4,
                                    const float4* __restrict__ be4, const float4* __restrict__ mn4,
                                    const float4* __restrict__ vr4,
                                    const float* __restrict__ Wd, const float* __restrict__ bd,
                                    float* __restrict__ out, int N)
{
    __shared__ float wd[F_H * 2];
    wd[threadIdx.x] = Wd[threadIdx.x];
    __syncthreads();

    int wid  = (blockIdx.x * blockDim.x + threadIdx.x) >> 5;
    int lane = threadIdx.x & 31;
    if (wid >= N) return;
    float4 a0 = gather_sum(msg, g_row[wid], g_cur[wid], lane);

    float4 r = make_float4(0.f, 0.f, 0.f, 0.f);
    acc_row(res, wid, lane, r);
    float4 bb = __ldg(b4 + lane);
    float4 gm = __ldg(g4 + lane);
    float4 be = __ldg(be4 + lane);
    float4 mn = __ldg(mn4 + lane);
    float4 vr = __ldg(vr4 + lane);
    float h0 = (fmaxf(a0.x + bb.x, 0.f) + r.x - mn.x) * rsqrtf(vr.x + EPS) * gm.x + be.x;
    float h1 = (fmaxf(a0.y + bb.y, 0.f) + r.y - mn.y) * rsqrtf(vr.y + EPS) * gm.y + be.y;
    float h2 = (fmaxf(a0.z + bb.z, 0.f) + r.z - mn.z) * rsqrtf(vr.z + EPS) * gm.z + be.z;
    float h3 = (fmaxf(a0.w + bb.w, 0.f) + r.w - mn.w) * rsqrtf(vr.w + EPS) * gm.w + be.w;

    int c = lane * 4;
    float l0 = h0 * wd[(c + 0) * 2] + h1 * wd[(c + 1) * 2] +
               h2 * wd[(c + 2) * 2] + h3 * wd[(c + 3) * 2];
    float l1 = h0 * wd[(c + 0) * 2 + 1] + h1 * wd[(c + 1) * 2 + 1] +
               h2 * wd[(c + 2) * 2 + 1] + h3 * wd[(c + 3) * 2 + 1];
#pragma unroll
    for (int off = 16; off > 0; off >>= 1) {
        l0 += __shfl_xor_sync(0xFFFFFFFFu, l0, off);
        l1 += __shfl_xor_sync(0xFFFFFFFFu, l1, off);
    }
    if (lane == 0) {
        l0 += __ldg(bd + 0);
        l1 += __ldg(bd + 1);
        float m  = fmaxf(l0, l1);
        float e0 = __expf(l0 - m), e1 = __expf(l1 - m);
        float inv = 1.f / (e0 + e1);
        out[(size_t)wid * 2 + 0] = e0 * inv;
        out[(size_t)wid * 2 + 1] = e1 * inv;
    }
}

// ---------------------------------------------------------------------------
extern "C" void kernel_launch(void* const* d_in, const int* in_sizes, int n_in,
                              void* d_out, int out_size)
{
    const float* in_feat = (const float*)d_in[0];
    const int*   src     = (const int*)d_in[1];
    const int*   dst     = (const int*)d_in[2];
    const float* W0   = (const float*)d_in[3];
    const float* b0   = (const float*)d_in[4];
    const float* Wr0  = (const float*)d_in[5];
    const float* br0  = (const float*)d_in[6];
    const float* g0   = (const float*)d_in[7];
    const float* be0  = (const float*)d_in[8];
    const float* m0   = (const float*)d_in[9];
    const float* v0   = (const float*)d_in[10];
    const float* W1   = (const float*)d_in[11];
    const float* b1   = (const float*)d_in[12];
    const float* Wr1  = (const float*)d_in[13];
    const float* br1  = (const float*)d_in[14];
    const float* g1   = (const float*)d_in[15];
    const float* be1  = (const float*)d_in[16];
    const float* m1   = (const float*)d_in[17];
    const float* v1   = (const float*)d_in[18];
    const float* Wd   = (const float*)d_in[19];
    const float* bd   = (const float*)d_in[20];

    const int N = in_sizes[0] / F_IN;   // 50000
    const int E = in_sizes[1];          // 800000

    constexpr int GEMM0_SMEM = 6 * 128 * 72 * 2;   // 110592 bytes (A,W,R x2 @ BK=64)
    constexpr int GEMM1_SMEM = 6 * 128 * 40 * 2;   // 61440 bytes

    struct Ctx {
        __nv_bfloat16 *msg, *res, *hbf, *w0t, *wr0t, *w1t, *wr1t;
        cudaStream_t s2;
        cudaEvent_t evFork, evJoin, evG0, evC;
        bool init;
    };
    static Ctx C = {};
    if (!C.init) {
        cudaGetSymbolAddress((void**)&C.msg,  g_msg);
        cudaGetSymbolAddress((void**)&C.res,  g_res);
        cudaGetSymbolAddress((void**)&C.hbf,  g_Hbf);
        cudaGetSymbolAddress((void**)&C.w0t,  g_W0t);
        cudaGetSymbolAddress((void**)&C.wr0t, g_Wr0t);
        cudaGetSymbolAddress((void**)&C.w1t,  g_W1t);
        cudaGetSymbolAddress((void**)&C.wr1t, g_Wr1t);
        cudaFuncSetAttribute(gemm0_kernel,
                             cudaFuncAttributeMaxDynamicSharedMemorySize, GEMM0_SMEM);
        cudaFuncSetAttribute(gemm1_kernel,
                             cudaFuncAttributeMaxDynamicSharedMemorySize, GEMM1_SMEM);
        cudaStreamCreateWithFlags(&C.s2, cudaStreamNonBlocking);
        cudaEventCreateWithFlags(&C.evFork, cudaEventDisableTiming);
        cudaEventCreateWithFlags(&C.evJoin, cudaEventDisableTiming);
        cudaEventCreateWithFlags(&C.evG0,   cudaEventDisableTiming);
        cudaEventCreateWithFlags(&C.evC,    cudaEventDisableTiming);
        C.init = true;
    }

    const int NB = (N + 255) / 256;
    const int eb = (E + 255) / 256;
    const int gemm_blocks = (N + 127) / 128;
    const int Nc = (((N / 2) + 127) / 128) * 128;   // 25088, chunk boundary
    const int cnt1 = N - Nc;                         // 24912

    // fork: W1 conv + CSR build on side stream
    cudaEventRecord(C.evFork, 0);
    cudaStreamWaitEvent(C.s2, C.evFork, 0);
    convW_kernel<F_H><<<128, 256, 0, C.s2>>>(W1, C.w1t, Wr1, C.wr1t);
    zero_kernel<<<NB, 256, 0, C.s2>>>(N);
    hist_kernel<<<eb, 256, 0, C.s2>>>(dst, E);
    scan_kernel<<<NB, 256, 0, C.s2>>>(N);
    fill_kernel<<<eb, 256, 0, C.s2>>>(src, dst, E);
    cudaEventRecord(C.evJoin, C.s2);

    // main stream: W0 conv + GEMM0
    convW_kernel<F_IN><<<1024, 256>>>(W0, C.w0t, Wr0, C.wr0t);
    gemm0_kernel<<<gemm_blocks, 256, GEMM0_SMEM>>>(in_feat, C.w0t, C.wr0t, br0,
                                                   C.msg, C.res, N);
    cudaEventRecord(C.evG0, 0);

    // side stream: layer-1 chunk B (needs msg/res + CSR; CSR same-stream)
    cudaStreamWaitEvent(C.s2, C.evG0, 0);
    gather0_kernel<<<(cnt1 + 7) / 8, 256, 0, C.s2>>>(
        C.msg, C.res, (const float4*)b0, (const float4*)g0, (const float4*)be0,
        (const float4*)m0, (const float4*)v0, (__nv_bfloat162*)C.hbf, Nc, N);
    gemm1_kernel<<<(cnt1 + 127) / 128, 256, GEMM1_SMEM, C.s2>>>(
        C.hbf + (size_t)Nc * F_H, C.w1t, C.wr1t, br1,
        C.msg + (size_t)Nc * F_H, C.res + (size_t)Nc * F_H, cnt1);
    cudaEventRecord(C.evC, C.s2);

    // main stream: layer-1 chunk A (needs CSR from side stream)
    cudaStreamWaitEvent(0, C.evJoin, 0);
    gather0_kernel<<<(Nc + 7) / 8, 256>>>(
        C.msg, C.res, (const float4*)b0, (const float4*)g0, (const float4*)be0,
        (const float4*)m0, (const float4*)v0, (__nv_bfloat162*)C.hbf, 0, Nc);
    gemm1_kernel<<<Nc / 128, 256, GEMM1_SMEM>>>(
        C.hbf, C.w1t, C.wr1t, br1, C.msg, C.res, Nc);

    // join both gemm1 halves, then final gather+head
    cudaStreamWaitEvent(0, C.evC, 0);
    gather1_head_kernel<<<(N + 7) / 8, 256>>>(
        C.msg, C.res, (const float4*)b1, (const float4*)g1, (const float4*)be1,
        (const float4*)m1, (const float4*)v1, Wd, bd, (float*)d_out, N);
}

// round 14
// speedup vs baseline: 1.4512x; 1.4512x over previous
#include <cuda_runtime.h>
#include <cuda_bf16.h>
#include <cstdint>

#define F_IN  1024
#define F_H   128
#define EPS   1e-5f
#define NODES_MAX 50048
#define EDGES_MAX 800000
#define SCAN_BLOCKS 256   // >= ceil(N/256)

// ------------------------- scratch (__device__ globals) ---------------------
__device__ __align__(256) __nv_bfloat16 g_msg[NODES_MAX * F_H];
__device__ __align__(256) __nv_bfloat16 g_res[NODES_MAX * F_H];
__device__ __align__(256) __nv_bfloat16 g_Hbf[NODES_MAX * F_H];
__device__ __align__(256) __nv_bfloat16 g_W0t [F_H * F_IN];
__device__ __align__(256) __nv_bfloat16 g_Wr0t[F_H * F_IN];
__device__ __align__(256) __nv_bfloat16 g_W1t [F_H * F_H];
__device__ __align__(256) __nv_bfloat16 g_Wr1t[F_H * F_H];
__device__ int g_deg [NODES_MAX];
__device__ int g_row [NODES_MAX];
__device__ int g_cur [NODES_MAX];
__device__ int g_esrc[EDGES_MAX];
__device__ unsigned int g_stat[SCAN_BLOCKS];   // lookback: (status<<30)|value

// ------------------------- weight conversion (smem transpose) ---------------
// [K,128] fp32 -> [128,K] bf16, 32x32 tiles, coalesced read AND write.
template <int K>
__global__ void convW_kernel(const float* __restrict__ wa, __nv_bfloat16* __restrict__ wta,
                             const float* __restrict__ wb, __nv_bfloat16* __restrict__ wtb)
{
    constexpr int KT    = K / 32;        // tiles along k
    constexpr int TILES = KT * 4;        // 128/32 = 4 tiles along n
    int b = blockIdx.x;
    const float* w; __nv_bfloat16* wt;
    if (b < TILES) { w = wa; wt = wta; }
    else           { w = wb; wt = wtb; b -= TILES; }
    const int k0 = (b % KT) * 32;
    const int n0 = (b / KT) * 32;

    __shared__ __nv_bfloat16 s[32][33];
    const int tx = threadIdx.x & 31;
    const int ty = threadIdx.x >> 5;     // 0..7
#pragma unroll
    for (int i = 0; i < 4; i++) {
        int kr = ty + i * 8;
        s[kr][tx] = __float2bfloat16(w[(size_t)(k0 + kr) * F_H + n0 + tx]);
    }
    __syncthreads();
#pragma unroll
    for (int i = 0; i < 4; i++) {
        int nr = ty + i * 8;
        wt[(size_t)(n0 + nr) * K + k0 + tx] = s[tx][nr];
    }
}

// ------------------------- CSR build (side stream) --------------------------
__global__ void zero_kernel(int N)
{
    int i = blockIdx.x * blockDim.x + threadIdx.x;
    if (i < N) g_deg[i] = 0;
    if (i < SCAN_BLOCKS) g_stat[i] = 0;
}
__global__ void hist_kernel(const int* __restrict__ dst, int E)
{
    int e = blockIdx.x * blockDim.x + threadIdx.x;
    if (e < E) atomicAdd(&g_deg[dst[e]], 1);
}
__global__ void scan_kernel(int N)
{
    __shared__ int s[256];
    __shared__ int s_prefix;
    const int t = threadIdx.x;
    const int bid = blockIdx.x;
    const int i = bid * 256 + t;
    int v = (i < N) ? g_deg[i] : 0;
    s[t] = v;
    __syncthreads();
#pragma unroll
    for (int off = 1; off < 256; off <<= 1) {
        int x = (t >= off) ? s[t - off] : 0;
        __syncthreads();
        s[t] += x;
        __syncthreads();
    }
    const int total = s[255];

    if (t == 0) {
        if (bid == 0) {
            __threadfence();
            atomicExch(&g_stat[0], (2u << 30) | (unsigned)total);
            s_prefix = 0;
        } else {
            __threadfence();
            atomicExch(&g_stat[bid], (1u << 30) | (unsigned)total);
            int ex = 0;
            int j = bid - 1;
            while (true) {
                unsigned w = atomicAdd(&g_stat[j], 0u);
                unsigned st = w >> 30;
                if (st == 0) continue;
                ex += (int)(w & 0x3FFFFFFFu);
                if (st == 2u) break;
                j--;
            }
            __threadfence();
            atomicExch(&g_stat[bid], (2u << 30) | (unsigned)(ex + total));
            s_prefix = ex;
        }
    }
    __syncthreads();
    if (i < N) {
        int r = s[t] - v + s_prefix;
        g_row[i] = r;
        g_cur[i] = r;
    }
}
__global__ void fill_kernel(const int* __restrict__ src, const int* __restrict__ dst, int E)
{
    int e = blockIdx.x * blockDim.x + threadIdx.x;
    if (e >= E) return;
    int d = dst[e];
    int pos = atomicAdd(&g_cur[d], 1);
    g_esrc[pos] = src[e];
}

// ------------------------- mma helper ---------------------------------------
__device__ __forceinline__ void mma_bf16(float* c, const uint32_t* a, const uint32_t* b)
{
    asm volatile(
        "mma.sync.aligned.m16n8k16.row.col.f32.bf16.bf16.f32 "
        "{%0,%1,%2,%3}, {%4,%5,%6,%7}, {%8,%9}, {%0,%1,%2,%3};"
        : "+f"(c[0]), "+f"(c[1]), "+f"(c[2]), "+f"(c[3])
        : "r"(a[0]), "r"(a[1]), "r"(a[2]), "r"(a[3]), "r"(b[0]), "r"(b[1]));
}

// ------------------------- GEMM0: fp32 X, fused convert, dual output --------
// R11 config: BM=128, BK=32, 256 thr, occ-1, single A read, double-buffered A,
// 3-stage W/R cp.async pipeline.
__global__ void __launch_bounds__(256) gemm0_kernel(
    const float* __restrict__ Xf, const __nv_bfloat16* __restrict__ Wt,
    const __nv_bfloat16* __restrict__ Wrt, const float* __restrict__ br,
    __nv_bfloat16* __restrict__ out_msg, __nv_bfloat16* __restrict__ out_res, int M)
{
    constexpr int KD = F_IN, BM = 128, BK = 32;
    constexpr int NIT = KD / BK;      // 32
    constexpr int SA = 40;            // bf16 row stride (32 + 8 pad)
    constexpr int TILE = BM * SA;     // 5120 bf16 per stage
    extern __shared__ __align__(16) __nv_bfloat16 smem[];
    __nv_bfloat16* sA = smem;                 // 2 stages
    __nv_bfloat16* sW = smem + 2 * TILE;      // 3 stages
    __nv_bfloat16* sR = smem + 5 * TILE;      // 3 stages

    const int t = threadIdx.x;
    const int bm = blockIdx.x * BM;
    const int lane = t & 31;
    const int w    = t >> 5;
    const int wm   = (w & 1) * 64;
    const int wn   = (w >> 1) * 32;
    const int g    = lane >> 2;
    const int t4   = lane & 3;

    const uint32_t sA_u = (uint32_t)__cvta_generic_to_shared(sA);
    const uint32_t sW_u = (uint32_t)__cvta_generic_to_shared(sW);
    const uint32_t sR_u = (uint32_t)__cvta_generic_to_shared(sR);

    // A staging: row = t&127, half = t>>7 (16 fp32 each)
    const int arow = t & 127;
    const int ah   = t >> 7;
    const bool aok = (bm + arow) < M;
    const float* aptr_base = Xf + (size_t)(bm + arow) * KD + ah * 16;

    float4 areg[4];
    auto loadA = [&](int it) {
        const float4* p = (const float4*)(aptr_base + it * BK);
        if (aok) { areg[0] = p[0]; areg[1] = p[1]; areg[2] = p[2]; areg[3] = p[3]; }
        else     { areg[0] = areg[1] = areg[2] = areg[3] = make_float4(0,0,0,0); }
    };
    auto convA = [&](int stg) {
        uint4 lo, hi;
        __nv_bfloat162 p;
        p = __float22bfloat162_rn(make_float2(areg[0].x, areg[0].y)); lo.x = *(uint32_t*)&p;
        p = __float22bfloat162_rn(make_float2(areg[0].z, areg[0].w)); lo.y = *(uint32_t*)&p;
        p = __float22bfloat162_rn(make_float2(areg[1].x, areg[1].y)); lo.z = *(uint32_t*)&p;
        p = __float22bfloat162_rn(make_float2(areg[1].z, areg[1].w)); lo.w = *(uint32_t*)&p;
        p = __float22bfloat162_rn(make_float2(areg[2].x, areg[2].y)); hi.x = *(uint32_t*)&p;
        p = __float22bfloat162_rn(make_float2(areg[2].z, areg[2].w)); hi.y = *(uint32_t*)&p;
        p = __float22bfloat162_rn(make_float2(areg[3].x, areg[3].y)); hi.z = *(uint32_t*)&p;
        p = __float22bfloat162_rn(make_float2(areg[3].z, areg[3].w)); hi.w = *(uint32_t*)&p;
        uint32_t a = sA_u + (uint32_t)((stg * TILE + arow * SA + ah * 16) * 2);
        asm volatile("st.shared.v4.b32 [%0], {%1,%2,%3,%4};"
                     :: "r"(a), "r"(lo.x), "r"(lo.y), "r"(lo.z), "r"(lo.w));
        asm volatile("st.shared.v4.b32 [%0], {%1,%2,%3,%4};"
                     :: "r"(a + 16), "r"(hi.x), "r"(hi.y), "r"(hi.z), "r"(hi.w));
    };
    auto loadWR = [&](int it, int stg) {
        const int k0 = it * BK;
#pragma unroll
        for (int i = 0; i < 2; i++) {
            int lin = t + i * 256;
            int m = lin >> 2, q = lin & 3;
            uint32_t doff = (uint32_t)((stg * TILE + m * SA + q * 8) * 2);
            const __nv_bfloat16* wsrc = Wt + (size_t)m * KD + k0 + q * 8;
            asm volatile("cp.async.cg.shared.global [%0], [%1], 16, 16;\n"
                         :: "r"(sW_u + doff), "l"(wsrc));
            const __nv_bfloat16* rsrc = Wrt + (size_t)m * KD + k0 + q * 8;
            asm volatile("cp.async.cg.shared.global [%0], [%1], 16, 16;\n"
                         :: "r"(sR_u + doff), "l"(rsrc));
        }
        asm volatile("cp.async.commit_group;\n");
    };

    float acc[2][4][4][4];
#pragma unroll
    for (int o = 0; o < 2; o++)
#pragma unroll
        for (int i = 0; i < 4; i++)
#pragma unroll
            for (int j = 0; j < 4; j++)
#pragma unroll
                for (int k = 0; k < 4; k++) acc[o][i][j][k] = 0.f;

    loadWR(0, 0);
    loadWR(1, 1);
    loadA(0);
    convA(0);      // A stage 0 ready (published by first sync)
    loadA(1);      // stage 1 in regs

    const int mrow = lane & 15;
    const int ksel = (lane >> 4) * 8;
    const int b_nrow = ((lane >> 4) & 1) * 8 + (lane & 7);
    const int b_koff = ((lane >> 3) & 1) * 8;

    for (int it = 0; it < NIT; ++it) {
        const int stgA = it & 1;
        const int stgB = it % 3;
        if (it + 2 < NIT) {
            loadWR(it + 2, (it + 2) % 3);
            asm volatile("cp.async.wait_group 2;\n");
        } else if (it + 1 < NIT) {
            asm volatile("cp.async.wait_group 1;\n");
        } else {
            asm volatile("cp.async.wait_group 0;\n");
        }
        __syncthreads();   // publishes sA[stgA] + sW/sR[stgB]

        const uint32_t A_u = sA_u + (uint32_t)(stgA * TILE * 2);
        const uint32_t W_u = sW_u + (uint32_t)(stgB * TILE * 2);
        const uint32_t R_u = sR_u + (uint32_t)(stgB * TILE * 2);

#pragma unroll
        for (int ks = 0; ks < 2; ks++) {
            const int kb = ks * 16;
            uint32_t a[4][4];
#pragma unroll
            for (int ma = 0; ma < 4; ma++) {
                uint32_t addr = A_u + (uint32_t)(((wm + ma * 16 + mrow) * SA + kb + ksel) * 2);
                asm volatile("ldmatrix.sync.aligned.m8n8.x4.shared.b16 {%0,%1,%2,%3}, [%4];"
                             : "=r"(a[ma][0]), "=r"(a[ma][1]), "=r"(a[ma][2]), "=r"(a[ma][3])
                             : "r"(addr));
            }
#pragma unroll
            for (int o = 0; o < 2; o++) {
                const uint32_t B_u = o ? R_u : W_u;
#pragma unroll
                for (int pr = 0; pr < 2; pr++) {
                    uint32_t b0, b1, b2, b3;
                    uint32_t addr = B_u + (uint32_t)(((wn + pr * 16 + b_nrow) * SA + kb + b_koff) * 2);
                    asm volatile("ldmatrix.sync.aligned.m8n8.x4.shared.b16 {%0,%1,%2,%3}, [%4];"
                                 : "=r"(b0), "=r"(b1), "=r"(b2), "=r"(b3)
                                 : "r"(addr));
                    uint32_t bl[2] = {b0, b1};
                    uint32_t bh[2] = {b2, b3};
#pragma unroll
                    for (int ma = 0; ma < 4; ma++) {
                        mma_bf16(acc[o][ma][pr * 2],     a[ma], bl);
                        mma_bf16(acc[o][ma][pr * 2 + 1], a[ma], bh);
                    }
                }
            }
        }
        // Write A for iter it+1 into the other A stage (1 sync/iter scheme).
        if (it + 1 < NIT) {
            convA(stgA ^ 1);
            if (it + 2 < NIT) loadA(it + 2);
        }
    }

    // Epilogue: bf16 outputs; res gets +br then relu
#pragma unroll
    for (int o = 0; o < 2; o++) {
        __nv_bfloat16* __restrict__ out = o ? out_res : out_msg;
#pragma unroll
        for (int nb = 0; nb < 4; nb++) {
            const int col = wn + nb * 8 + 2 * t4;
            float2 brv = make_float2(0.f, 0.f);
            if (o) { brv.x = br[col]; brv.y = br[col + 1]; }
#pragma unroll
            for (int ma = 0; ma < 4; ma++) {
                int row0 = bm + wm + ma * 16 + g;
                float* c = acc[o][ma][nb];
                float2 v0 = make_float2(c[0], c[1]);
                float2 v1 = make_float2(c[2], c[3]);
                if (o) {
                    v0.x = fmaxf(v0.x + brv.x, 0.f); v0.y = fmaxf(v0.y + brv.y, 0.f);
                    v1.x = fmaxf(v1.x + brv.x, 0.f); v1.y = fmaxf(v1.y + brv.y, 0.f);
                }
                __nv_bfloat162 p0, p1;
                p0.x = __float2bfloat16(v0.x); p0.y = __float2bfloat16(v0.y);
                p1.x = __float2bfloat16(v1.x); p1.y = __float2bfloat16(v1.y);
                if (row0 < M)
                    *(__nv_bfloat162*)(out + (size_t)row0 * F_H + col) = p0;
                if (row0 + 8 < M)
                    *(__nv_bfloat162*)(out + (size_t)(row0 + 8) * F_H + col) = p1;
            }
        }
    }
}

// ------------------------- GEMM1: bf16 input, dual output (R6) --------------
// Works on a row-chunk: caller offsets Xb/out pointers; M = chunk row count.
__global__ void __launch_bounds__(256) gemm1_kernel(
    const __nv_bfloat16* __restrict__ Xb, const __nv_bfloat16* __restrict__ Wt,
    const __nv_bfloat16* __restrict__ Wrt, const float* __restrict__ br,
    __nv_bfloat16* __restrict__ out_msg, __nv_bfloat16* __restrict__ out_res, int M)
{
    constexpr int KD = F_H, BM = 128, BK = 32;
    constexpr int NIT = KD / BK;   // 4
    constexpr int SA = 40;
    constexpr int TILE = BM * SA;
    extern __shared__ __align__(16) __nv_bfloat16 smem[];
    __nv_bfloat16* sA = smem;
    __nv_bfloat16* sW = smem + 2 * TILE;
    __nv_bfloat16* sR = smem + 4 * TILE;

    const int t = threadIdx.x;
    const int bm = blockIdx.x * BM;
    const int lane = t & 31;
    const int w    = t >> 5;
    const int wm   = (w & 1) * 64;
    const int wn   = (w >> 1) * 32;
    const int g    = lane >> 2;
    const int t4   = lane & 3;

    const uint32_t sA_u = (uint32_t)__cvta_generic_to_shared(sA);
    const uint32_t sW_u = (uint32_t)__cvta_generic_to_shared(sW);
    const uint32_t sR_u = (uint32_t)__cvta_generic_to_shared(sR);

    float acc[2][4][4][4];
#pragma unroll
    for (int o = 0; o < 2; o++)
#pragma unroll
        for (int i = 0; i < 4; i++)
#pragma unroll
            for (int j = 0; j < 4; j++)
#pragma unroll
                for (int k = 0; k < 4; k++) acc[o][i][j][k] = 0.f;

    auto loadStage = [&](int it, int stg) {
        const int k0 = it * BK;
#pragma unroll
        for (int i = 0; i < 2; i++) {
            int lin = t + i * 256;
            int m = lin >> 2, q = lin & 3;
            uint32_t doff = (uint32_t)((stg * TILE + m * SA + q * 8) * 2);
            const __nv_bfloat16* asrc = Xb + (size_t)(bm + m) * KD + k0 + q * 8;
            int sz = (bm + m < M) ? 16 : 0;
            asm volatile("cp.async.cg.shared.global [%0], [%1], 16, %2;\n"
                         :: "r"(sA_u + doff), "l"(asrc), "r"(sz));
            const __nv_bfloat16* wsrc = Wt + (size_t)m * KD + k0 + q * 8;
            asm volatile("cp.async.cg.shared.global [%0], [%1], 16, 16;\n"
                         :: "r"(sW_u + doff), "l"(wsrc));
            const __nv_bfloat16* rsrc = Wrt + (size_t)m * KD + k0 + q * 8;
            asm volatile("cp.async.cg.shared.global [%0], [%1], 16, 16;\n"
                         :: "r"(sR_u + doff), "l"(rsrc));
        }
        asm volatile("cp.async.commit_group;\n");
    };

    loadStage(0, 0);

    const int mrow = lane & 15;
    const int ksel = (lane >> 4) * 8;
    const int b_nrow = ((lane >> 4) & 1) * 8 + (lane & 7);
    const int b_koff = ((lane >> 3) & 1) * 8;

    for (int it = 0; it < NIT; ++it) {
        const int stg = it & 1;
        if (it + 1 < NIT) {
            loadStage(it + 1, stg ^ 1);
            asm volatile("cp.async.wait_group 1;\n");
        } else {
            asm volatile("cp.async.wait_group 0;\n");
        }
        __syncthreads();

        const uint32_t A_u = sA_u + (uint32_t)(stg * TILE * 2);
        const uint32_t W_u = sW_u + (uint32_t)(stg * TILE * 2);
        const uint32_t R_u = sR_u + (uint32_t)(stg * TILE * 2);

#pragma unroll
        for (int ks = 0; ks < 2; ks++) {
            const int kb = ks * 16;
            uint32_t a[4][4];
#pragma unroll
            for (int ma = 0; ma < 4; ma++) {
                uint32_t addr = A_u + (uint32_t)(((wm + ma * 16 + mrow) * SA + kb + ksel) * 2);
                asm volatile("ldmatrix.sync.aligned.m8n8.x4.shared.b16 {%0,%1,%2,%3}, [%4];"
                             : "=r"(a[ma][0]), "=r"(a[ma][1]), "=r"(a[ma][2]), "=r"(a[ma][3])
                             : "r"(addr));
            }
#pragma unroll
            for (int o = 0; o < 2; o++) {
                const uint32_t B_u = o ? R_u : W_u;
#pragma unroll
                for (int pr = 0; pr < 2; pr++) {
                    uint32_t b0, b1, b2, b3;
                    uint32_t addr = B_u + (uint32_t)(((wn + pr * 16 + b_nrow) * SA + kb + b_koff) * 2);
                    asm volatile("ldmatrix.sync.aligned.m8n8.x4.shared.b16 {%0,%1,%2,%3}, [%4];"
                                 : "=r"(b0), "=r"(b1), "=r"(b2), "=r"(b3)
                                 : "r"(addr));
                    uint32_t bl[2] = {b0, b1};
                    uint32_t bh[2] = {b2, b3};
#pragma unroll
                    for (int ma = 0; ma < 4; ma++) {
                        mma_bf16(acc[o][ma][pr * 2],     a[ma], bl);
                        mma_bf16(acc[o][ma][pr * 2 + 1], a[ma], bh);
                    }
                }
            }
        }
        __syncthreads();
    }

#pragma unroll
    for (int o = 0; o < 2; o++) {
        __nv_bfloat16* __restrict__ out = o ? out_res : out_msg;
#pragma unroll
        for (int nb = 0; nb < 4; nb++) {
            const int col = wn + nb * 8 + 2 * t4;
            float2 brv = make_float2(0.f, 0.f);
            if (o) { brv.x = br[col]; brv.y = br[col + 1]; }
#pragma unroll
            for (int ma = 0; ma < 4; ma++) {
                int row0 = bm + wm + ma * 16 + g;
                float* c = acc[o][ma][nb];
                float2 v0 = make_float2(c[0], c[1]);
                float2 v1 = make_float2(c[2], c[3]);
                if (o) {
                    v0.x = fmaxf(v0.x + brv.x, 0.f); v0.y = fmaxf(v0.y + brv.y, 0.f);
                    v1.x = fmaxf(v1.x + brv.x, 0.f); v1.y = fmaxf(v1.y + brv.y, 0.f);
                }
                __nv_bfloat162 p0, p1;
                p0.x = __float2bfloat16(v0.x); p0.y = __float2bfloat16(v0.y);
                p1.x = __float2bfloat16(v1.x); p1.y = __float2bfloat16(v1.y);
                if (row0 < M)
                    *(__nv_bfloat162*)(out + (size_t)row0 * F_H + col) = p0;
                if (row0 + 8 < M)
                    *(__nv_bfloat162*)(out + (size_t)(row0 + 8) * F_H + col) = p1;
            }
        }
    }
}

// ------------------------- gather + fused epilogues -------------------------
__device__ __forceinline__ void acc_row(const __nv_bfloat16* __restrict__ base,
                                        int node, int lane, float4& a)
{
    uint2 q = __ldg((const uint2*)(base + (size_t)node * F_H) + lane);
    __nv_bfloat162 x0 = *(__nv_bfloat162*)&q.x;
    __nv_bfloat162 x1 = *(__nv_bfloat162*)&q.y;
    float2 f0 = __bfloat1622float2(x0);
    float2 f1 = __bfloat1622float2(x1);
    a.x += f0.x; a.y += f0.y; a.z += f1.x; a.w += f1.y;
}

__device__ __forceinline__ float4 gather_sum(const __nv_bfloat16* __restrict__ msg,
                                             int s, int e, int lane)
{
    float4 a0 = make_float4(0.f, 0.f, 0.f, 0.f);
    float4 a1 = make_float4(0.f, 0.f, 0.f, 0.f);
    float4 a2 = make_float4(0.f, 0.f, 0.f, 0.f);
    float4 a3 = make_float4(0.f, 0.f, 0.f, 0.f);
    int i = s;
    for (; i + 4 <= e; i += 4) {
        int u0 = __ldg(&g_esrc[i]),     u1 = __ldg(&g_esrc[i + 1]);
        int u2 = __ldg(&g_esrc[i + 2]), u3 = __ldg(&g_esrc[i + 3]);
        acc_row(msg, u0, lane, a0);
        acc_row(msg, u1, lane, a1);
        acc_row(msg, u2, lane, a2);
        acc_row(msg, u3, lane, a3);
    }
    for (; i < e; i++) acc_row(msg, __ldg(&g_esrc[i]), lane, a0);
    a0.x += a1.x + a2.x + a3.x;
    a0.y += a1.y + a2.y + a3.y;
    a0.z += a1.z + a2.z + a3.z;
    a0.w += a1.w + a2.w + a3.w;
    return a0;
}

// Nodes [n0, n1): agg -> relu(+b) + res -> BN -> bf16 h1
__global__ void gather0_kernel(const __nv_bfloat16* __restrict__ msg,
                               const __nv_bfloat16* __restrict__ res,
                               const float4* __restrict__ b4, const float4* __restrict__ g4,
                               const float4* __restrict__ be4, const float4* __restrict__ mn4,
                               const float4* __restrict__ vr4,
                               __nv_bfloat162* __restrict__ hout, int n0, int n1)
{
    int wid  = n0 + ((blockIdx.x * blockDim.x + threadIdx.x) >> 5);
    int lane = threadIdx.x & 31;
    if (wid >= n1) return;
    float4 a0 = gather_sum(msg, g_row[wid], g_cur[wid], lane);

    float4 r = make_float4(0.f, 0.f, 0.f, 0.f);
    acc_row(res, wid, lane, r);
    float4 bb = __ldg(b4 + lane);
    float4 gm = __ldg(g4 + lane);
    float4 be = __ldg(be4 + lane);
    float4 mn = __ldg(mn4 + lane);
    float4 vr = __ldg(vr4 + lane);
    float o0 = (fmaxf(a0.x + bb.x, 0.f) + r.x - mn.x) * rsqrtf(vr.x + EPS) * gm.x + be.x;
    float o1 = (fmaxf(a0.y + bb.y, 0.f) + r.y - mn.y) * rsqrtf(vr.y + EPS) * gm.y + be.y;
    float o2 = (fmaxf(a0.z + bb.z, 0.f) + r.z - mn.z) * rsqrtf(vr.z + EPS) * gm.z + be.z;
    float o3 = (fmaxf(a0.w + bb.w, 0.f) + r.w - mn.w) * rsqrtf(vr.w + EPS) * gm.w + be.w;

    __nv_bfloat162 p0, p1;
    p0.x = __float2bfloat16(o0); p0.y = __float2bfloat16(o1);
    p1.x = __float2bfloat16(o2); p1.y = __float2bfloat16(o3);
    hout[(size_t)wid * (F_H / 2) + lane * 2]     = p0;
    hout[(size_t)wid * (F_H / 2) + lane * 2 + 1] = p1;
}

__global__ void gather1_head_kernel(const __nv_bfloat16* __restrict__ msg,
                                    const __nv_bfloat16* __restrict__ res,
                                    const float4* __restrict__ b4, const float4* __restrict__ g4,
                                    const float4* __restrict__ be4, const float4* __restrict__ mn4,
                                    const float4* __restrict__ vr4,
                                    const float* __restrict__ Wd, const float* __restrict__ bd,
                                    float* __restrict__ out, int N)
{
    __shared__ float wd[F_H * 2];
    wd[threadIdx.x] = Wd[threadIdx.x];
    __syncthreads();

    int wid  = (blockIdx.x * blockDim.x + threadIdx.x) >> 5;
    int lane = threadIdx.x & 31;
    if (wid >= N) return;
    float4 a0 = gather_sum(msg, g_row[wid], g_cur[wid], lane);

    float4 r = make_float4(0.f, 0.f, 0.f, 0.f);
    acc_row(res, wid, lane, r);
    float4 bb = __ldg(b4 + lane);
    float4 gm = __ldg(g4 + lane);
    float4 be = __ldg(be4 + lane);
    float4 mn = __ldg(mn4 + lane);
    float4 vr = __ldg(vr4 + lane);
    float h0 = (fmaxf(a0.x + bb.x, 0.f) + r.x - mn.x) * rsqrtf(vr.x + EPS) * gm.x + be.x;
    float h1 = (fmaxf(a0.y + bb.y, 0.f) + r.y - mn.y) * rsqrtf(vr.y + EPS) * gm.y + be.y;
    float h2 = (fmaxf(a0.z + bb.z, 0.f) + r.z - mn.z) * rsqrtf(vr.z + EPS) * gm.z + be.z;
    float h3 = (fmaxf(a0.w + bb.w, 0.f) + r.w - mn.w) * rsqrtf(vr.w + EPS) * gm.w + be.w;

    int c = lane * 4;
    float l0 = h0 * wd[(c + 0) * 2] + h1 * wd[(c + 1) * 2] +
               h2 * wd[(c + 2) * 2] + h3 * wd[(c + 3) * 2];
    float l1 = h0 * wd[(c + 0) * 2 + 1] + h1 * wd[(c + 1) * 2 + 1] +
               h2 * wd[(c + 2) * 2 + 1] + h3 * wd[(c + 3) * 2 + 1];
#pragma unroll
    for (int off = 16; off > 0; off >>= 1) {
        l0 += __shfl_xor_sync(0xFFFFFFFFu, l0, off);
        l1 += __shfl_xor_sync(0xFFFFFFFFu, l1, off);
    }
    if (lane == 0) {
        l0 += __ldg(bd + 0);
        l1 += __ldg(bd + 1);
        float m  = fmaxf(l0, l1);
        float e0 = __expf(l0 - m), e1 = __expf(l1 - m);
        float inv = 1.f / (e0 + e1);
        out[(size_t)wid * 2 + 0] = e0 * inv;
        out[(size_t)wid * 2 + 1] = e1 * inv;
    }
}

// ---------------------------------------------------------------------------
extern "C" void kernel_launch(void* const* d_in, const int* in_sizes, int n_in,
                              void* d_out, int out_size)
{
    const float* in_feat = (const float*)d_in[0];
    const int*   src     = (const int*)d_in[1];
    const int*   dst     = (const int*)d_in[2];
    const float* W0   = (const float*)d_in[3];
    const float* b0   = (const float*)d_in[4];
    const float* Wr0  = (const float*)d_in[5];
    const float* br0  = (const float*)d_in[6];
    const float* g0   = (const float*)d_in[7];
    const float* be0  = (const float*)d_in[8];
    const float* m0   = (const float*)d_in[9];
    const float* v0   = (const float*)d_in[10];
    const float* W1   = (const float*)d_in[11];
    const float* b1   = (const float*)d_in[12];
    const float* Wr1  = (const float*)d_in[13];
    const float* br1  = (const float*)d_in[14];
    const float* g1   = (const float*)d_in[15];
    const float* be1  = (const float*)d_in[16];
    const float* m1   = (const float*)d_in[17];
    const float* v1   = (const float*)d_in[18];
    const float* Wd   = (const float*)d_in[19];
    const float* bd   = (const float*)d_in[20];

    const int N = in_sizes[0] / F_IN;   // 50000
    const int E = in_sizes[1];          // 800000

    constexpr int GEMM0_SMEM = 8 * 128 * 40 * 2;   // 81920 bytes (A x2, W x3, R x3)
    constexpr int GEMM1_SMEM = 6 * 128 * 40 * 2;   // 61440 bytes

    struct Ctx {
        __nv_bfloat16 *msg, *res, *hbf, *w0t, *wr0t, *w1t, *wr1t;
        cudaStream_t s2;
        cudaEvent_t evFork, evJoin, evG0, evC;
        bool init;
    };
    static Ctx C = {};
    if (!C.init) {
        cudaGetSymbolAddress((void**)&C.msg,  g_msg);
        cudaGetSymbolAddress((void**)&C.res,  g_res);
        cudaGetSymbolAddress((void**)&C.hbf,  g_Hbf);
        cudaGetSymbolAddress((void**)&C.w0t,  g_W0t);
        cudaGetSymbolAddress((void**)&C.wr0t, g_Wr0t);
        cudaGetSymbolAddress((void**)&C.w1t,  g_W1t);
        cudaGetSymbolAddress((void**)&C.wr1t, g_Wr1t);
        cudaFuncSetAttribute(gemm0_kernel,
                             cudaFuncAttributeMaxDynamicSharedMemorySize, GEMM0_SMEM);
        cudaFuncSetAttribute(gemm1_kernel,
                             cudaFuncAttributeMaxDynamicSharedMemorySize, GEMM1_SMEM);
        cudaStreamCreateWithFlags(&C.s2, cudaStreamNonBlocking);
        cudaEventCreateWithFlags(&C.evFork, cudaEventDisableTiming);
        cudaEventCreateWithFlags(&C.evJoin, cudaEventDisableTiming);
        cudaEventCreateWithFlags(&C.evG0,   cudaEventDisableTiming);
        cudaEventCreateWithFlags(&C.evC,    cudaEventDisableTiming);
        C.init = true;
    }

    const int NB = (N + 255) / 256;
    const int eb = (E + 255) / 256;
    const int gemm_blocks = (N + 127) / 128;
    const int Nc = (((N / 2) + 127) / 128) * 128;   // 25088, chunk boundary
    const int cnt1 = N - Nc;                         // 24912

    // fork: W1 conv + CSR build on side stream
    cudaEventRecord(C.evFork, 0);
    cudaStreamWaitEvent(C.s2, C.evFork, 0);
    convW_kernel<F_H><<<32, 256, 0, C.s2>>>(W1, C.w1t, Wr1, C.wr1t);
    zero_kernel<<<NB, 256, 0, C.s2>>>(N);
    hist_kernel<<<eb, 256, 0, C.s2>>>(dst, E);
    scan_kernel<<<NB, 256, 0, C.s2>>>(N);
    fill_kernel<<<eb, 256, 0, C.s2>>>(src, dst, E);
    cudaEventRecord(C.evJoin, C.s2);

    // main stream: W0 conv + GEMM0
    convW_kernel<F_IN><<<256, 256>>>(W0, C.w0t, Wr0, C.wr0t);
    gemm0_kernel<<<gemm_blocks, 256, GEMM0_SMEM>>>(in_feat, C.w0t, C.wr0t, br0,
                                                   C.msg, C.res, N);
    cudaEventRecord(C.evG0, 0);

    // side stream: layer-1 chunk B (needs msg/res + CSR; CSR same-stream)
    cudaStreamWaitEvent(C.s2, C.evG0, 0);
    gather0_kernel<<<(cnt1 + 7) / 8, 256, 0, C.s2>>>(
        C.msg, C.res, (const float4*)b0, (const float4*)g0, (const float4*)be0,
        (const float4*)m0, (const float4*)v0, (__nv_bfloat162*)C.hbf, Nc, N);
    gemm1_kernel<<<(cnt1 + 127) / 128, 256, GEMM1_SMEM, C.s2>>>(
        C.hbf + (size_t)Nc * F_H, C.w1t, C.wr1t, br1,
        C.msg + (size_t)Nc * F_H, C.res + (size_t)Nc * F_H, cnt1);
    cudaEventRecord(C.evC, C.s2);

    // main stream: layer-1 chunk A (needs CSR from side stream)
    cudaStreamWaitEvent(0, C.evJoin, 0);
    gather0_kernel<<<(Nc + 7) / 8, 256>>>(
        C.msg, C.res, (const float4*)b0, (const float4*)g0, (const float4*)be0,
        (const float4*)m0, (const float4*)v0, (__nv_bfloat162*)C.hbf, 0, Nc);
    gemm1_kernel<<<Nc / 128, 256, GEMM1_SMEM>>>(
        C.hbf, C.w1t, C.wr1t, br1, C.msg, C.res, Nc);

    // join both gemm1 halves, then final gather+head
    cudaStreamWaitEvent(0, C.evC, 0);
    gather1_head_kernel<<<(N + 7) / 8, 256>>>(
        C.msg, C.res, (const float4*)b1, (const float4*)g1, (const float4*)be1,
        (const float4*)m1, (const float4*)v1, Wd, bd, (float*)d_out, N);
}

// round 16
// speedup vs baseline: 1.4610x; 1.0067x over previous
#include <cuda_runtime.h>
#include <cuda_bf16.h>
#include <cstdint>

#define F_IN  1024
#define F_H   128
#define EPS   1e-5f
#define NODES_MAX 50048
#define EDGES_MAX 800000
#define SCAN_BLOCKS 256   // >= ceil(N/256)

// ------------------------- scratch (__device__ globals) ---------------------
__device__ __align__(256) __nv_bfloat16 g_msg[NODES_MAX * F_H];
__device__ __align__(256) __nv_bfloat16 g_res[NODES_MAX * F_H];
__device__ __align__(256) __nv_bfloat16 g_Hbf[NODES_MAX * F_H];
__device__ __align__(256) __nv_bfloat16 g_W0t [F_H * F_IN];
__device__ __align__(256) __nv_bfloat16 g_Wr0t[F_H * F_IN];
__device__ __align__(256) __nv_bfloat16 g_W1t [F_H * F_H];
__device__ __align__(256) __nv_bfloat16 g_Wr1t[F_H * F_H];
__device__ int g_deg [NODES_MAX];
__device__ int g_row [NODES_MAX];
__device__ int g_cur [NODES_MAX];
__device__ int g_esrc[EDGES_MAX];
__device__ unsigned int g_stat[SCAN_BLOCKS];   // lookback: (status<<30)|value

// ------------------------- weight conversion (smem transpose) ---------------
// [K,128] fp32 -> [128,K] bf16, 32x32 tiles, coalesced read AND write.
template <int K>
__global__ void convW_kernel(const float* __restrict__ wa, __nv_bfloat16* __restrict__ wta,
                             const float* __restrict__ wb, __nv_bfloat16* __restrict__ wtb)
{
    constexpr int KT    = K / 32;        // tiles along k
    constexpr int TILES = KT * 4;        // 128/32 = 4 tiles along n
    int b = blockIdx.x;
    const float* w; __nv_bfloat16* wt;
    if (b < TILES) { w = wa; wt = wta; }
    else           { w = wb; wt = wtb; b -= TILES; }
    const int k0 = (b % KT) * 32;
    const int n0 = (b / KT) * 32;

    __shared__ __nv_bfloat16 s[32][33];
    const int tx = threadIdx.x & 31;
    const int ty = threadIdx.x >> 5;     // 0..7
#pragma unroll
    for (int i = 0; i < 4; i++) {
        int kr = ty + i * 8;
        s[kr][tx] = __float2bfloat16(w[(size_t)(k0 + kr) * F_H + n0 + tx]);
    }
    __syncthreads();
#pragma unroll
    for (int i = 0; i < 4; i++) {
        int nr = ty + i * 8;
        wt[(size_t)(n0 + nr) * K + k0 + tx] = s[tx][nr];
    }
}

// ------------------------- CSR build (side stream) --------------------------
__global__ void zero_kernel(int N)
{
    int i = blockIdx.x * blockDim.x + threadIdx.x;
    if (i < N) g_deg[i] = 0;
    if (i < SCAN_BLOCKS) g_stat[i] = 0;
}
__global__ void hist_kernel(const int* __restrict__ dst, int E)
{
    int e = blockIdx.x * blockDim.x + threadIdx.x;
    if (e < E) atomicAdd(&g_deg[dst[e]], 1);
}
__global__ void scan_kernel(int N)
{
    __shared__ int s[256];
    __shared__ int s_prefix;
    const int t = threadIdx.x;
    const int bid = blockIdx.x;
    const int i = bid * 256 + t;
    int v = (i < N) ? g_deg[i] : 0;
    s[t] = v;
    __syncthreads();
#pragma unroll
    for (int off = 1; off < 256; off <<= 1) {
        int x = (t >= off) ? s[t - off] : 0;
        __syncthreads();
        s[t] += x;
        __syncthreads();
    }
    const int total = s[255];

    if (t == 0) {
        if (bid == 0) {
            __threadfence();
            atomicExch(&g_stat[0], (2u << 30) | (unsigned)total);
            s_prefix = 0;
        } else {
            __threadfence();
            atomicExch(&g_stat[bid], (1u << 30) | (unsigned)total);
            int ex = 0;
            int j = bid - 1;
            while (true) {
                unsigned w = atomicAdd(&g_stat[j], 0u);
                unsigned st = w >> 30;
                if (st == 0) continue;
                ex += (int)(w & 0x3FFFFFFFu);
                if (st == 2u) break;
                j--;
            }
            __threadfence();
            atomicExch(&g_stat[bid], (2u << 30) | (unsigned)(ex + total));
            s_prefix = ex;
        }
    }
    __syncthreads();
    if (i < N) {
        int r = s[t] - v + s_prefix;
        g_row[i] = r;
        g_cur[i] = r;
    }
}
__global__ void fill_kernel(const int* __restrict__ src, const int* __restrict__ dst, int E)
{
    int e = blockIdx.x * blockDim.x + threadIdx.x;
    if (e >= E) return;
    int d = dst[e];
    int pos = atomicAdd(&g_cur[d], 1);
    g_esrc[pos] = src[e];
}

// ------------------------- mma helper ---------------------------------------
__device__ __forceinline__ void mma_bf16(float* c, const uint32_t* a, const uint32_t* b)
{
    asm volatile(
        "mma.sync.aligned.m16n8k16.row.col.f32.bf16.bf16.f32 "
        "{%0,%1,%2,%3}, {%4,%5,%6,%7}, {%8,%9}, {%0,%1,%2,%3};"
        : "+f"(c[0]), "+f"(c[1]), "+f"(c[2]), "+f"(c[3])
        : "r"(a[0]), "r"(a[1]), "r"(a[2]), "r"(a[3]), "r"(b[0]), "r"(b[1]));
}

// ------------------------- GEMM0: fp32 X, fused convert, dual output --------
// R14 ordering (convA/loadA at iteration tail). Race-free W/R pipeline:
// wait_group 1 BEFORE the sync (drains group `it`), loadWR(it+2) issued
// AFTER the sync so its cp.async writes can't race iter it-1's readers.
__global__ void __launch_bounds__(256) gemm0_kernel(
    const float* __restrict__ Xf, const __nv_bfloat16* __restrict__ Wt,
    const __nv_bfloat16* __restrict__ Wrt, const float* __restrict__ br,
    __nv_bfloat16* __restrict__ out_msg, __nv_bfloat16* __restrict__ out_res, int M)
{
    constexpr int KD = F_IN, BM = 128, BK = 32;
    constexpr int NIT = KD / BK;      // 32
    constexpr int SA = 40;            // bf16 row stride (32 + 8 pad)
    constexpr int TILE = BM * SA;     // 5120 bf16 per stage
    extern __shared__ __align__(16) __nv_bfloat16 smem[];
    __nv_bfloat16* sA = smem;                 // 2 stages
    __nv_bfloat16* sW = smem + 2 * TILE;      // 3 stages
    __nv_bfloat16* sR = smem + 5 * TILE;      // 3 stages

    const int t = threadIdx.x;
    const int bm = blockIdx.x * BM;
    const int lane = t & 31;
    const int w    = t >> 5;
    const int wm   = (w & 1) * 64;
    const int wn   = (w >> 1) * 32;
    const int g    = lane >> 2;
    const int t4   = lane & 3;

    const uint32_t sA_u = (uint32_t)__cvta_generic_to_shared(sA);
    const uint32_t sW_u = (uint32_t)__cvta_generic_to_shared(sW);
    const uint32_t sR_u = (uint32_t)__cvta_generic_to_shared(sR);

    // A staging: row = t&127, half = t>>7 (16 fp32 each)
    const int arow = t & 127;
    const int ah   = t >> 7;
    const bool aok = (bm + arow) < M;
    const float* aptr_base = Xf + (size_t)(bm + arow) * KD + ah * 16;

    float4 areg[4];
    auto loadA = [&](int it) {
        const float4* p = (const float4*)(aptr_base + it * BK);
        if (aok) { areg[0] = p[0]; areg[1] = p[1]; areg[2] = p[2]; areg[3] = p[3]; }
        else     { areg[0] = areg[1] = areg[2] = areg[3] = make_float4(0,0,0,0); }
    };
    auto convA = [&](int stg) {
        uint4 lo, hi;
        __nv_bfloat162 p;
        p = __float22bfloat162_rn(make_float2(areg[0].x, areg[0].y)); lo.x = *(uint32_t*)&p;
        p = __float22bfloat162_rn(make_float2(areg[0].z, areg[0].w)); lo.y = *(uint32_t*)&p;
        p = __float22bfloat162_rn(make_float2(areg[1].x, areg[1].y)); lo.z = *(uint32_t*)&p;
        p = __float22bfloat162_rn(make_float2(areg[1].z, areg[1].w)); lo.w = *(uint32_t*)&p;
        p = __float22bfloat162_rn(make_float2(areg[2].x, areg[2].y)); hi.x = *(uint32_t*)&p;
        p = __float22bfloat162_rn(make_float2(areg[2].z, areg[2].w)); hi.y = *(uint32_t*)&p;
        p = __float22bfloat162_rn(make_float2(areg[3].x, areg[3].y)); hi.z = *(uint32_t*)&p;
        p = __float22bfloat162_rn(make_float2(areg[3].z, areg[3].w)); hi.w = *(uint32_t*)&p;
        uint32_t a = sA_u + (uint32_t)((stg * TILE + arow * SA + ah * 16) * 2);
        asm volatile("st.shared.v4.b32 [%0], {%1,%2,%3,%4};"
                     :: "r"(a), "r"(lo.x), "r"(lo.y), "r"(lo.z), "r"(lo.w));
        asm volatile("st.shared.v4.b32 [%0], {%1,%2,%3,%4};"
                     :: "r"(a + 16), "r"(hi.x), "r"(hi.y), "r"(hi.z), "r"(hi.w));
    };
    auto loadWR = [&](int it, int stg) {
        const int k0 = it * BK;
#pragma unroll
        for (int i = 0; i < 2; i++) {
            int lin = t + i * 256;
            int m = lin >> 2, q = lin & 3;
            uint32_t doff = (uint32_t)((stg * TILE + m * SA + q * 8) * 2);
            const __nv_bfloat16* wsrc = Wt + (size_t)m * KD + k0 + q * 8;
            asm volatile("cp.async.cg.shared.global [%0], [%1], 16, 16;\n"
                         :: "r"(sW_u + doff), "l"(wsrc));
            const __nv_bfloat16* rsrc = Wrt + (size_t)m * KD + k0 + q * 8;
            asm volatile("cp.async.cg.shared.global [%0], [%1], 16, 16;\n"
                         :: "r"(sR_u + doff), "l"(rsrc));
        }
        asm volatile("cp.async.commit_group;\n");
    };

    float acc[2][4][4][4];
#pragma unroll
    for (int o = 0; o < 2; o++)
#pragma unroll
        for (int i = 0; i < 4; i++)
#pragma unroll
            for (int j = 0; j < 4; j++)
#pragma unroll
                for (int k = 0; k < 4; k++) acc[o][i][j][k] = 0.f;

    loadWR(0, 0);
    loadWR(1, 1);
    loadA(0);
    convA(0);      // A stage 0 ready (published by first sync)
    loadA(1);      // stage 1 in regs

    const int mrow = lane & 15;
    const int ksel = (lane >> 4) * 8;
    const int b_nrow = ((lane >> 4) & 1) * 8 + (lane & 7);
    const int b_koff = ((lane >> 3) & 1) * 8;

    for (int it = 0; it < NIT; ++it) {
        const int stgA = it & 1;
        const int stgB = it % 3;
        // Drain group `it` (outstanding pre-sync = {it, it+1}).
        if (it + 1 < NIT) {
            asm volatile("cp.async.wait_group 1;\n");
        } else {
            asm volatile("cp.async.wait_group 0;\n");
        }
        __syncthreads();   // publishes sA[stgA] + sW/sR[stgB]; all iter-1 readers done

        // Race-free: issue the it+2 weight loads only after the barrier, so
        // their writes to stage (it+2)%3 cannot overlap iter it-1's reads.
        if (it + 2 < NIT) loadWR(it + 2, (it + 2) % 3);

        const uint32_t A_u = sA_u + (uint32_t)(stgA * TILE * 2);
        const uint32_t W_u = sW_u + (uint32_t)(stgB * TILE * 2);
        const uint32_t R_u = sR_u + (uint32_t)(stgB * TILE * 2);

#pragma unroll
        for (int ks = 0; ks < 2; ks++) {
            const int kb = ks * 16;
            uint32_t a[4][4];
#pragma unroll
            for (int ma = 0; ma < 4; ma++) {
                uint32_t addr = A_u + (uint32_t)(((wm + ma * 16 + mrow) * SA + kb + ksel) * 2);
                asm volatile("ldmatrix.sync.aligned.m8n8.x4.shared.b16 {%0,%1,%2,%3}, [%4];"
                             : "=r"(a[ma][0]), "=r"(a[ma][1]), "=r"(a[ma][2]), "=r"(a[ma][3])
                             : "r"(addr));
            }
#pragma unroll
            for (int o = 0; o < 2; o++) {
                const uint32_t B_u = o ? R_u : W_u;
#pragma unroll
                for (int pr = 0; pr < 2; pr++) {
                    uint32_t b0, b1, b2, b3;
                    uint32_t addr = B_u + (uint32_t)(((wn + pr * 16 + b_nrow) * SA + kb + b_koff) * 2);
                    asm volatile("ldmatrix.sync.aligned.m8n8.x4.shared.b16 {%0,%1,%2,%3}, [%4];"
                                 : "=r"(b0), "=r"(b1), "=r"(b2), "=r"(b3)
                                 : "r"(addr));
                    uint32_t bl[2] = {b0, b1};
                    uint32_t bh[2] = {b2, b3};
#pragma unroll
                    for (int ma = 0; ma < 4; ma++) {
                        mma_bf16(acc[o][ma][pr * 2],     a[ma], bl);
                        mma_bf16(acc[o][ma][pr * 2 + 1], a[ma], bh);
                    }
                }
            }
        }
        // Tail (R14-proven ordering): write A for iter it+1 into the other
        // stage; prefetch it+2. Safe: all warps passed this iter's sync, so
        // no warp still reads sA[stgA^1] (last read was iter it-1).
        if (it + 1 < NIT) {
            convA(stgA ^ 1);
            if (it + 2 < NIT) loadA(it + 2);
        }
    }

    // Epilogue: bf16 outputs; res gets +br then relu
#pragma unroll
    for (int o = 0; o < 2; o++) {
        __nv_bfloat16* __restrict__ out = o ? out_res : out_msg;
#pragma unroll
        for (int nb = 0; nb < 4; nb++) {
            const int col = wn + nb * 8 + 2 * t4;
            float2 brv = make_float2(0.f, 0.f);
            if (o) { brv.x = br[col]; brv.y = br[col + 1]; }
#pragma unroll
            for (int ma = 0; ma < 4; ma++) {
                int row0 = bm + wm + ma * 16 + g;
                float* c = acc[o][ma][nb];
                float2 v0 = make_float2(c[0], c[1]);
                float2 v1 = make_float2(c[2], c[3]);
                if (o) {
                    v0.x = fmaxf(v0.x + brv.x, 0.f); v0.y = fmaxf(v0.y + brv.y, 0.f);
                    v1.x = fmaxf(v1.x + brv.x, 0.f); v1.y = fmaxf(v1.y + brv.y, 0.f);
                }
                __nv_bfloat162 p0, p1;
                p0.x = __float2bfloat16(v0.x); p0.y = __float2bfloat16(v0.y);
                p1.x = __float2bfloat16(v1.x); p1.y = __float2bfloat16(v1.y);
                if (row0 < M)
                    *(__nv_bfloat162*)(out + (size_t)row0 * F_H + col) = p0;
                if (row0 + 8 < M)
                    *(__nv_bfloat162*)(out + (size_t)(row0 + 8) * F_H + col) = p1;
            }
        }
    }
}

// ------------------------- GEMM1: bf16 input, dual output (R6) --------------
// Works on a row-chunk: caller offsets Xb/out pointers; M = chunk row count.
__global__ void __launch_bounds__(256) gemm1_kernel(
    const __nv_bfloat16* __restrict__ Xb, const __nv_bfloat16* __restrict__ Wt,
    const __nv_bfloat16* __restrict__ Wrt, const float* __restrict__ br,
    __nv_bfloat16* __restrict__ out_msg, __nv_bfloat16* __restrict__ out_res, int M)
{
    constexpr int KD = F_H, BM = 128, BK = 32;
    constexpr int NIT = KD / BK;   // 4
    constexpr int SA = 40;
    constexpr int TILE = BM * SA;
    extern __shared__ __align__(16) __nv_bfloat16 smem[];
    __nv_bfloat16* sA = smem;
    __nv_bfloat16* sW = smem + 2 * TILE;
    __nv_bfloat16* sR = smem + 4 * TILE;

    const int t = threadIdx.x;
    const int bm = blockIdx.x * BM;
    const int lane = t & 31;
    const int w    = t >> 5;
    const int wm   = (w & 1) * 64;
    const int wn   = (w >> 1) * 32;
    const int g    = lane >> 2;
    const int t4   = lane & 3;

    const uint32_t sA_u = (uint32_t)__cvta_generic_to_shared(sA);
    const uint32_t sW_u = (uint32_t)__cvta_generic_to_shared(sW);
    const uint32_t sR_u = (uint32_t)__cvta_generic_to_shared(sR);

    float acc[2][4][4][4];
#pragma unroll
    for (int o = 0; o < 2; o++)
#pragma unroll
        for (int i = 0; i < 4; i++)
#pragma unroll
            for (int j = 0; j < 4; j++)
#pragma unroll
                for (int k = 0; k < 4; k++) acc[o][i][j][k] = 0.f;

    auto loadStage = [&](int it, int stg) {
        const int k0 = it * BK;
#pragma unroll
        for (int i = 0; i < 2; i++) {
            int lin = t + i * 256;
            int m = lin >> 2, q = lin & 3;
            uint32_t doff = (uint32_t)((stg * TILE + m * SA + q * 8) * 2);
            const __nv_bfloat16* asrc = Xb + (size_t)(bm + m) * KD + k0 + q * 8;
            int sz = (bm + m < M) ? 16 : 0;
            asm volatile("cp.async.cg.shared.global [%0], [%1], 16, %2;\n"
                         :: "r"(sA_u + doff), "l"(asrc), "r"(sz));
            const __nv_bfloat16* wsrc = Wt + (size_t)m * KD + k0 + q * 8;
            asm volatile("cp.async.cg.shared.global [%0], [%1], 16, 16;\n"
                         :: "r"(sW_u + doff), "l"(wsrc));
            const __nv_bfloat16* rsrc = Wrt + (size_t)m * KD + k0 + q * 8;
            asm volatile("cp.async.cg.shared.global [%0], [%1], 16, 16;\n"
                         :: "r"(sR_u + doff), "l"(rsrc));
        }
        asm volatile("cp.async.commit_group;\n");
    };

    loadStage(0, 0);

    const int mrow = lane & 15;
    const int ksel = (lane >> 4) * 8;
    const int b_nrow = ((lane >> 4) & 1) * 8 + (lane & 7);
    const int b_koff = ((lane >> 3) & 1) * 8;

    for (int it = 0; it < NIT; ++it) {
        const int stg = it & 1;
        if (it + 1 < NIT) {
            loadStage(it + 1, stg ^ 1);
            asm volatile("cp.async.wait_group 1;\n");
        } else {
            asm volatile("cp.async.wait_group 0;\n");
        }
        __syncthreads();

        const uint32_t A_u = sA_u + (uint32_t)(stg * TILE * 2);
        const uint32_t W_u = sW_u + (uint32_t)(stg * TILE * 2);
        const uint32_t R_u = sR_u + (uint32_t)(stg * TILE * 2);

#pragma unroll
        for (int ks = 0; ks < 2; ks++) {
            const int kb = ks * 16;
            uint32_t a[4][4];
#pragma unroll
            for (int ma = 0; ma < 4; ma++) {
                uint32_t addr = A_u + (uint32_t)(((wm + ma * 16 + mrow) * SA + kb + ksel) * 2);
                asm volatile("ldmatrix.sync.aligned.m8n8.x4.shared.b16 {%0,%1,%2,%3}, [%4];"
                             : "=r"(a[ma][0]), "=r"(a[ma][1]), "=r"(a[ma][2]), "=r"(a[ma][3])
                             : "r"(addr));
            }
#pragma unroll
            for (int o = 0; o < 2; o++) {
                const uint32_t B_u = o ? R_u : W_u;
#pragma unroll
                for (int pr = 0; pr < 2; pr++) {
                    uint32_t b0, b1, b2, b3;
                    uint32_t addr = B_u + (uint32_t)(((wn + pr * 16 + b_nrow) * SA + kb + b_koff) * 2);
                    asm volatile("ldmatrix.sync.aligned.m8n8.x4.shared.b16 {%0,%1,%2,%3}, [%4];"
                                 : "=r"(b0), "=r"(b1), "=r"(b2), "=r"(b3)
                                 : "r"(addr));
                    uint32_t bl[2] = {b0, b1};
                    uint32_t bh[2] = {b2, b3};
#pragma unroll
                    for (int ma = 0; ma < 4; ma++) {
                        mma_bf16(acc[o][ma][pr * 2],     a[ma], bl);
                        mma_bf16(acc[o][ma][pr * 2 + 1], a[ma], bh);
                    }
                }
            }
        }
        __syncthreads();
    }

#pragma unroll
    for (int o = 0; o < 2; o++) {
        __nv_bfloat16* __restrict__ out = o ? out_res : out_msg;
#pragma unroll
        for (int nb = 0; nb < 4; nb++) {
            const int col = wn + nb * 8 + 2 * t4;
            float2 brv = make_float2(0.f, 0.f);
            if (o) { brv.x = br[col]; brv.y = br[col + 1]; }
#pragma unroll
            for (int ma = 0; ma < 4; ma++) {
                int row0 = bm + wm + ma * 16 + g;
                float* c = acc[o][ma][nb];
                float2 v0 = make_float2(c[0], c[1]);
                float2 v1 = make_float2(c[2], c[3]);
                if (o) {
                    v0.x = fmaxf(v0.x + brv.x, 0.f); v0.y = fmaxf(v0.y + brv.y, 0.f);
                    v1.x = fmaxf(v1.x + brv.x, 0.f); v1.y = fmaxf(v1.y + brv.y, 0.f);
                }
                __nv_bfloat162 p0, p1;
                p0.x = __float2bfloat16(v0.x); p0.y = __float2bfloat16(v0.y);
                p1.x = __float2bfloat16(v1.x); p1.y = __float2bfloat16(v1.y);
                if (row0 < M)
                    *(__nv_bfloat162*)(out + (size_t)row0 * F_H + col) = p0;
                if (row0 + 8 < M)
                    *(__nv_bfloat162*)(out + (size_t)(row0 + 8) * F_H + col) = p1;
            }
        }
    }
}

// ------------------------- gather + fused epilogues -------------------------
__device__ __forceinline__ void acc_row(const __nv_bfloat16* __restrict__ base,
                                        int node, int lane, float4& a)
{
    uint2 q = __ldg((const uint2*)(base + (size_t)node * F_H) + lane);
    __nv_bfloat162 x0 = *(__nv_bfloat162*)&q.x;
    __nv_bfloat162 x1 = *(__nv_bfloat162*)&q.y;
    float2 f0 = __bfloat1622float2(x0);
    float2 f1 = __bfloat1622float2(x1);
    a.x += f0.x; a.y += f0.y; a.z += f1.x; a.w += f1.y;
}

__device__ __forceinline__ float4 gather_sum(const __nv_bfloat16* __restrict__ msg,
                                             int s, int e, int lane)
{
    float4 a0 = make_float4(0.f, 0.f, 0.f, 0.f);
    float4 a1 = make_float4(0.f, 0.f, 0.f, 0.f);
    float4 a2 = make_float4(0.f, 0.f, 0.f, 0.f);
    float4 a3 = make_float4(0.f, 0.f, 0.f, 0.f);
    int i = s;
    for (; i + 4 <= e; i += 4) {
        int u0 = __ldg(&g_esrc[i]),     u1 = __ldg(&g_esrc[i + 1]);
        int u2 = __ldg(&g_esrc[i + 2]), u3 = __ldg(&g_esrc[i + 3]);
        acc_row(msg, u0, lane, a0);
        acc_row(msg, u1, lane, a1);
        acc_row(msg, u2, lane, a2);
        acc_row(msg, u3, lane, a3);
    }
    for (; i < e; i++) acc_row(msg, __ldg(&g_esrc[i]), lane, a0);
    a0.x += a1.x + a2.x + a3.x;
    a0.y += a1.y + a2.y + a3.y;
    a0.z += a1.z + a2.z + a3.z;
    a0.w += a1.w + a2.w + a3.w;
    return a0;
}

// Nodes [n0, n1): agg -> relu(+b) + res -> BN -> bf16 h1
__global__ void gather0_kernel(const __nv_bfloat16* __restrict__ msg,
                               const __nv_bfloat16* __restrict__ res,
                               const float4* __restrict__ b4, const float4* __restrict__ g4,
                               const float4* __restrict__ be4, const float4* __restrict__ mn4,
                               const float4* __restrict__ vr4,
                               __nv_bfloat162* __restrict__ hout, int n0, int n1)
{
    int wid  = n0 + ((blockIdx.x * blockDim.x + threadIdx.x) >> 5);
    int lane = threadIdx.x & 31;
    if (wid >= n1) return;
    float4 a0 = gather_sum(msg, g_row[wid], g_cur[wid], lane);

    float4 r = make_float4(0.f, 0.f, 0.f, 0.f);
    acc_row(res, wid, lane, r);
    float4 bb = __ldg(b4 + lane);
    float4 gm = __ldg(g4 + lane);
    float4 be = __ldg(be4 + lane);
    float4 mn = __ldg(mn4 + lane);
    float4 vr = __ldg(vr4 + lane);
    float o0 = (fmaxf(a0.x + bb.x, 0.f) + r.x - mn.x) * rsqrtf(vr.x + EPS) * gm.x + be.x;
    float o1 = (fmaxf(a0.y + bb.y, 0.f) + r.y - mn.y) * rsqrtf(vr.y + EPS) * gm.y + be.y;
    float o2 = (fmaxf(a0.z + bb.z, 0.f) + r.z - mn.z) * rsqrtf(vr.z + EPS) * gm.z + be.z;
    float o3 = (fmaxf(a0.w + bb.w, 0.f) + r.w - mn.w) * rsqrtf(vr.w + EPS) * gm.w + be.w;

    __nv_bfloat162 p0, p1;
    p0.x = __float2bfloat16(o0); p0.y = __float2bfloat16(o1);
    p1.x = __float2bfloat16(o2); p1.y = __float2bfloat16(o3);
    hout[(size_t)wid * (F_H / 2) + lane * 2]     = p0;
    hout[(size_t)wid * (F_H / 2) + lane * 2 + 1] = p1;
}

__global__ void gather1_head_kernel(const __nv_bfloat16* __restrict__ msg,
                                    const __nv_bfloat16* __restrict__ res,
                                    const float4* __restrict__ b4, const float4* __restrict__ g4,
                                    const float4* __restrict__ be4, const float4* __restrict__ mn4,
                                    const float4* __restrict__ vr4,
                                    const float* __restrict__ Wd, const float* __restrict__ bd,
                                    float* __restrict__ out, int N)
{
    __shared__ float wd[F_H * 2];
    wd[threadIdx.x] = Wd[threadIdx.x];
    __syncthreads();

    int wid  = (blockIdx.x * blockDim.x + threadIdx.x) >> 5;
    int lane = threadIdx.x & 31;
    if (wid >= N) return;
    float4 a0 = gather_sum(msg, g_row[wid], g_cur[wid], lane);

    float4 r = make_float4(0.f, 0.f, 0.f, 0.f);
    acc_row(res, wid, lane, r);
    float4 bb = __ldg(b4 + lane);
    float4 gm = __ldg(g4 + lane);
    float4 be = __ldg(be4 + lane);
    float4 mn = __ldg(mn4 + lane);
    float4 vr = __ldg(vr4 + lane);
    float h0 = (fmaxf(a0.x + bb.x, 0.f) + r.x - mn.x) * rsqrtf(vr.x + EPS) * gm.x + be.x;
    float h1 = (fmaxf(a0.y + bb.y, 0.f) + r.y - mn.y) * rsqrtf(vr.y + EPS) * gm.y + be.y;
    float h2 = (fmaxf(a0.z + bb.z, 0.f) + r.z - mn.z) * rsqrtf(vr.z + EPS) * gm.z + be.z;
    float h3 = (fmaxf(a0.w + bb.w, 0.f) + r.w - mn.w) * rsqrtf(vr.w + EPS) * gm.w + be.w;

    int c = lane * 4;
    float l0 = h0 * wd[(c + 0) * 2] + h1 * wd[(c + 1) * 2] +
               h2 * wd[(c + 2) * 2] + h3 * wd[(c + 3) * 2];
    float l1 = h0 * wd[(c + 0) * 2 + 1] + h1 * wd[(c + 1) * 2 + 1] +
               h2 * wd[(c + 2) * 2 + 1] + h3 * wd[(c + 3) * 2 + 1];
#pragma unroll
    for (int off = 16; off > 0; off >>= 1) {
        l0 += __shfl_xor_sync(0xFFFFFFFFu, l0, off);
        l1 += __shfl_xor_sync(0xFFFFFFFFu, l1, off);
    }
    if (lane == 0) {
        l0 += __ldg(bd + 0);
        l1 += __ldg(bd + 1);
        float m  = fmaxf(l0, l1);
        float e0 = __expf(l0 - m), e1 = __expf(l1 - m);
        float inv = 1.f / (e0 + e1);
        out[(size_t)wid * 2 + 0] = e0 * inv;
        out[(size_t)wid * 2 + 1] = e1 * inv;
    }
}

// ---------------------------------------------------------------------------
extern "C" void kernel_launch(void* const* d_in, const int* in_sizes, int n_in,
                              void* d_out, int out_size)
{
    const float* in_feat = (const float*)d_in[0];
    const int*   src     = (const int*)d_in[1];
    const int*   dst     = (const int*)d_in[2];
    const float* W0   = (const float*)d_in[3];
    const float* b0   = (const float*)d_in[4];
    const float* Wr0  = (const float*)d_in[5];
    const float* br0  = (const float*)d_in[6];
    const float* g0   = (const float*)d_in[7];
    const float* be0  = (const float*)d_in[8];
    const float* m0   = (const float*)d_in[9];
    const float* v0   = (const float*)d_in[10];
    const float* W1   = (const float*)d_in[11];
    const float* b1   = (const float*)d_in[12];
    const float* Wr1  = (const float*)d_in[13];
    const float* br1  = (const float*)d_in[14];
    const float* g1   = (const float*)d_in[15];
    const float* be1  = (const float*)d_in[16];
    const float* m1   = (const float*)d_in[17];
    const float* v1   = (const float*)d_in[18];
    const float* Wd   = (const float*)d_in[19];
    const float* bd   = (const float*)d_in[20];

    const int N = in_sizes[0] / F_IN;   // 50000
    const int E = in_sizes[1];          // 800000

    constexpr int GEMM0_SMEM = 8 * 128 * 40 * 2;   // 81920 bytes (A x2, W x3, R x3)
    constexpr int GEMM1_SMEM = 6 * 128 * 40 * 2;   // 61440 bytes

    struct Ctx {
        __nv_bfloat16 *msg, *res, *hbf, *w0t, *wr0t, *w1t, *wr1t;
        cudaStream_t s2;
        cudaEvent_t evFork, evJoin, evG0, evC;
        bool init;
    };
    static Ctx C = {};
    if (!C.init) {
        cudaGetSymbolAddress((void**)&C.msg,  g_msg);
        cudaGetSymbolAddress((void**)&C.res,  g_res);
        cudaGetSymbolAddress((void**)&C.hbf,  g_Hbf);
        cudaGetSymbolAddress((void**)&C.w0t,  g_W0t);
        cudaGetSymbolAddress((void**)&C.wr0t, g_Wr0t);
        cudaGetSymbolAddress((void**)&C.w1t,  g_W1t);
        cudaGetSymbolAddress((void**)&C.wr1t, g_Wr1t);
        cudaFuncSetAttribute(gemm0_kernel,
                             cudaFuncAttributeMaxDynamicSharedMemorySize, GEMM0_SMEM);
        cudaFuncSetAttribute(gemm1_kernel,
                             cudaFuncAttributeMaxDynamicSharedMemorySize, GEMM1_SMEM);
        cudaStreamCreateWithFlags(&C.s2, cudaStreamNonBlocking);
        cudaEventCreateWithFlags(&C.evFork, cudaEventDisableTiming);
        cudaEventCreateWithFlags(&C.evJoin, cudaEventDisableTiming);
        cudaEventCreateWithFlags(&C.evG0,   cudaEventDisableTiming);
        cudaEventCreateWithFlags(&C.evC,    cudaEventDisableTiming);
        C.init = true;
    }

    const int NB = (N + 255) / 256;
    const int eb = (E + 255) / 256;
    const int gemm_blocks = (N + 127) / 128;
    const int Nc = (((N / 2) + 127) / 128) * 128;   // 25088, chunk boundary
    const int cnt1 = N - Nc;                         // 24912

    // fork: W1 conv + CSR build on side stream
    cudaEventRecord(C.evFork, 0);
    cudaStreamWaitEvent(C.s2, C.evFork, 0);
    convW_kernel<F_H><<<32, 256, 0, C.s2>>>(W1, C.w1t, Wr1, C.wr1t);
    zero_kernel<<<NB, 256, 0, C.s2>>>(N);
    hist_kernel<<<eb, 256, 0, C.s2>>>(dst, E);
    scan_kernel<<<NB, 256, 0, C.s2>>>(N);
    fill_kernel<<<eb, 256, 0, C.s2>>>(src, dst, E);
    cudaEventRecord(C.evJoin, C.s2);

    // main stream: W0 conv + GEMM0
    convW_kernel<F_IN><<<256, 256>>>(W0, C.w0t, Wr0, C.wr0t);
    gemm0_kernel<<<gemm_blocks, 256, GEMM0_SMEM>>>(in_feat, C.w0t, C.wr0t, br0,
                                                   C.msg, C.res, N);
    cudaEventRecord(C.evG0, 0);

    // side stream: layer-1 chunk B (needs msg/res + CSR; CSR same-stream)
    cudaStreamWaitEvent(C.s2, C.evG0, 0);
    gather0_kernel<<<(cnt1 + 7) / 8, 256, 0, C.s2>>>(
        C.msg, C.res, (const float4*)b0, (const float4*)g0, (const float4*)be0,
        (const float4*)m0, (const float4*)v0, (__nv_bfloat162*)C.hbf, Nc, N);
    gemm1_kernel<<<(cnt1 + 127) / 128, 256, GEMM1_SMEM, C.s2>>>(
        C.hbf + (size_t)Nc * F_H, C.w1t, C.wr1t, br1,
        C.msg + (size_t)Nc * F_H, C.res + (size_t)Nc * F_H, cnt1);
    cudaEventRecord(C.evC, C.s2);

    // main stream: layer-1 chunk A (needs CSR from side stream)
    cudaStreamWaitEvent(0, C.evJoin, 0);
    gather0_kernel<<<(Nc + 7) / 8, 256>>>(
        C.msg, C.res, (const float4*)b0, (const float4*)g0, (const float4*)be0,
        (const float4*)m0, (const float4*)v0, (__nv_bfloat162*)C.hbf, 0, Nc);
    gemm1_kernel<<<Nc / 128, 256, GEMM1_SMEM>>>(
        C.hbf, C.w1t, C.wr1t, br1, C.msg, C.res, Nc);

    // join both gemm1 halves, then final gather+head
    cudaStreamWaitEvent(0, C.evC, 0);
    gather1_head_kernel<<<(N + 7) / 8, 256>>>(
        C.msg, C.res, (const float4*)b1, (const float4*)g1, (const float4*)be1,
        (const float4*)m1, (const float4*)v1, Wd, bd, (float*)d_out, N);
}